// round 7
// baseline (speedup 1.0000x reference)
#include <cuda_runtime.h>
#include <cfloat>
#include <cstddef>

#define B 64
#define TIN 256
#define F 64
#define H 1024
#define H3 3072
#define TGT 64
#define V 32000
#define BH (B*H)

typedef unsigned long long ULL;
typedef unsigned int uint;

__device__ float g_gi0[(size_t)TIN * B * H3];
__device__ float g_gi1[(size_t)TIN * B * H3];
__device__ float g_h0seq[(size_t)TIN * BH];
__device__ float g_enc[(size_t)TIN * BH];
__device__ float g_dh0[2 * BH];
__device__ float g_dh1[2 * BH];
__device__ float g_q[BH];
__device__ float g_cat[B * 2 * H];
__device__ float g_comb[BH];
__device__ ULL   g_keys[B];
__device__ unsigned long long g_bar64;   // encoder-only grid barrier

__device__ __forceinline__ void grid_sync() {
    __syncthreads();
    if (threadIdx.x == 0) {
        __threadfence();
        unsigned long long old = atomicAdd(&g_bar64, 1ULL);
        unsigned gen = (unsigned)(old >> 32);
        if ((unsigned)old == gridDim.x - 1) {
            atomicAdd(&g_bar64, (1ULL << 32) - (unsigned long long)gridDim.x);
        } else {
            while ((unsigned)((*(volatile unsigned long long*)&g_bar64) >> 32) == gen) { }
        }
        __threadfence();
    }
    __syncthreads();
}

__device__ __forceinline__ float sigmoidf_(float x) { return 1.f / (1.f + expf(-x)); }
__device__ __forceinline__ void fma2(ULL& d, ULL a, ULL b) {
    asm("fma.rn.f32x2 %0, %1, %2, %0;" : "+l"(d) : "l"(a), "l"(b));
}
__device__ __forceinline__ float2 unpack2(ULL v) {
    float2 r; asm("mov.b64 {%0, %1}, %2;" : "=f"(r.x), "=f"(r.y) : "l"(v)); return r;
}
__device__ __forceinline__ ULL splat2(float f) {
    ULL r; asm("mov.b64 %0, {%1, %1};" : "=l"(r) : "f"(f)); return r;
}
// total-order float key (matches '>' for non-NaN); monotone in value
__device__ __forceinline__ uint ord32(float f) {
    uint u = __float_as_uint(f);
    return u ^ ((u >> 31) ? 0xFFFFFFFFu : 0x80000000u);
}

// ============ FMA2 GEMM (bitwise-proven): C = A @ W^T + bias, tile 64x128 ============
__global__ __launch_bounds__(256) void gemm2_tn(
    const float* __restrict__ A, const float* __restrict__ W,
    const float* __restrict__ bias, float* __restrict__ C,
    int K, int lda, int ldw, int ldc)
{
    __shared__ __align__(16) ULL smu2[2 * 64 * 33];
    ULL* As2 = smu2;
    ULL* Ws2 = smu2 + 64 * 33;
    const int tid = threadIdx.x;
    const int tx = tid & 15, ty = tid >> 4;
    const int m0 = blockIdx.y * 64, n0 = blockIdx.x * 128;

    ULL acc[4][4];
#pragma unroll
    for (int r = 0; r < 4; r++)
#pragma unroll
        for (int q = 0; q < 4; q++) acc[r][q] = 0ULL;

    for (int k0 = 0; k0 < K; k0 += 32) {
        for (int i = tid; i < 2048; i += 256) {
            int m = i >> 5, k = i & 31;
            float v = A[(size_t)(m0 + m) * lda + k0 + k];
            ((float2*)As2)[m * 33 + k] = make_float2(v, v);
        }
        for (int i = tid; i < 2048; i += 256) {
            int pc = i >> 5, k = i & 31;
            int n_lo = n0 + (pc >> 4) * 32 + (pc & 15);
            ((float2*)Ws2)[pc * 33 + k] = make_float2(
                W[(size_t)n_lo * ldw + k0 + k], W[(size_t)(n_lo + 16) * ldw + k0 + k]);
        }
        __syncthreads();
#pragma unroll 8
        for (int k = 0; k < 32; k++) {
            ULL a0 = As2[ty * 33 + k], a1 = As2[(ty + 16) * 33 + k];
            ULL a2 = As2[(ty + 32) * 33 + k], a3 = As2[(ty + 48) * 33 + k];
            ULL w0 = Ws2[tx * 33 + k], w1 = Ws2[(16 + tx) * 33 + k];
            ULL w2 = Ws2[(32 + tx) * 33 + k], w3 = Ws2[(48 + tx) * 33 + k];
            fma2(acc[0][0], w0, a0); fma2(acc[0][1], w1, a0); fma2(acc[0][2], w2, a0); fma2(acc[0][3], w3, a0);
            fma2(acc[1][0], w0, a1); fma2(acc[1][1], w1, a1); fma2(acc[1][2], w2, a1); fma2(acc[1][3], w3, a1);
            fma2(acc[2][0], w0, a2); fma2(acc[2][1], w1, a2); fma2(acc[2][2], w2, a2); fma2(acc[2][3], w3, a2);
            fma2(acc[3][0], w0, a3); fma2(acc[3][1], w1, a3); fma2(acc[3][2], w2, a3); fma2(acc[3][3], w3, a3);
        }
        __syncthreads();
    }
#pragma unroll
    for (int r = 0; r < 4; r++) {
        int m = m0 + ty + 16 * r;
#pragma unroll
        for (int q = 0; q < 4; q++) {
            float2 v = unpack2(acc[r][q]);
            int n_lo = n0 + q * 32 + tx;
            C[(size_t)m * ldc + n_lo]      = v.x + bias[n_lo];
            C[(size_t)m * ldc + n_lo + 16] = v.y + bias[n_lo + 16];
        }
    }
}

// ============ persistent encoder recurrence — unchanged (proven) ============
#define WS_PITCH 1028
#define XS_PITCH 68
__global__ __launch_bounds__(256, 1) void enc_recur_kernel(
    const float* __restrict__ gi, long long gi_t_stride, long long gi_b_stride,
    const float* __restrict__ Whh, const float* __restrict__ bhh,
    float* __restrict__ hseq)
{
    extern __shared__ float sm[];
    float* ws = sm;
    float* xs = sm + 24 * WS_PITCH;

    const int tid = threadIdx.x;
    const int c = tid & 7, bq = tid >> 3;
    const int jb = blockIdx.x * 8;
    const int b0 = 2 * bq, b1 = b0 + 1;
    const int j = jb + c;

    for (int i = tid; i < 24 * 256; i += 256) {
        int r = i >> 8, kg = i & 255;
        int wr = (r >> 3) * H + jb + (r & 7);
        *(float4*)(ws + r * WS_PITCH + kg * 4) =
            *(const float4*)(Whh + (size_t)wr * H + kg * 4);
    }
    const float br = bhh[j], bz = bhh[H + j], bn = bhh[2 * H + j];
    __syncthreads();

    for (int t = 0; t < TIN; t++) {
        float ar0 = 0.f, ar1 = 0.f, az0 = 0.f, az1 = 0.f, an0 = 0.f, an1 = 0.f;
        const float* hprev = hseq + (size_t)(t - 1) * BH;
        if (t > 0) {
            for (int k0 = 0; k0 < H; k0 += 64) {
                for (int i = tid; i < 1024; i += 256) {
                    int b = i >> 4, kg = i & 15;
                    *(float4*)(xs + b * XS_PITCH + kg * 4) =
                        *(const float4*)(hprev + (size_t)b * H + k0 + kg * 4);
                }
                __syncthreads();
#pragma unroll
                for (int kk = 0; kk < 64; kk += 4) {
                    float4 x0 = *(const float4*)(xs + b0 * XS_PITCH + kk);
                    float4 x1 = *(const float4*)(xs + b1 * XS_PITCH + kk);
                    float4 w0 = *(const float4*)(ws + c * WS_PITCH + k0 + kk);
                    float4 w1 = *(const float4*)(ws + (8 + c) * WS_PITCH + k0 + kk);
                    float4 w2 = *(const float4*)(ws + (16 + c) * WS_PITCH + k0 + kk);
                    ar0 = fmaf(w0.x, x0.x, ar0); ar0 = fmaf(w0.y, x0.y, ar0);
                    ar0 = fmaf(w0.z, x0.z, ar0); ar0 = fmaf(w0.w, x0.w, ar0);
                    ar1 = fmaf(w0.x, x1.x, ar1); ar1 = fmaf(w0.y, x1.y, ar1);
                    ar1 = fmaf(w0.z, x1.z, ar1); ar1 = fmaf(w0.w, x1.w, ar1);
                    az0 = fmaf(w1.x, x0.x, az0); az0 = fmaf(w1.y, x0.y, az0);
                    az0 = fmaf(w1.z, x0.z, az0); az0 = fmaf(w1.w, x0.w, az0);
                    az1 = fmaf(w1.x, x1.x, az1); az1 = fmaf(w1.y, x1.y, az1);
                    az1 = fmaf(w1.z, x1.z, az1); az1 = fmaf(w1.w, x1.w, az1);
                    an0 = fmaf(w2.x, x0.x, an0); an0 = fmaf(w2.y, x0.y, an0);
                    an0 = fmaf(w2.z, x0.z, an0); an0 = fmaf(w2.w, x0.w, an0);
                    an1 = fmaf(w2.x, x1.x, an1); an1 = fmaf(w2.y, x1.y, an1);
                    an1 = fmaf(w2.z, x1.z, an1); an1 = fmaf(w2.w, x1.w, an1);
                }
                __syncthreads();
            }
        }
        const float* gr0 = gi + (size_t)b0 * gi_b_stride + (size_t)t * gi_t_stride;
        const float* gr1 = gi + (size_t)b1 * gi_b_stride + (size_t)t * gi_t_stride;
        float* hout = hseq + (size_t)t * BH;
        float hp0 = (t > 0) ? hprev[(size_t)b0 * H + j] : 0.f;
        float hp1 = (t > 0) ? hprev[(size_t)b1 * H + j] : 0.f;
        {
            float r = sigmoidf_(gr0[j] + ar0 + br);
            float z = sigmoidf_(gr0[H + j] + az0 + bz);
            float n = tanhf(gr0[2 * H + j] + r * (an0 + bn));
            hout[(size_t)b0 * H + j] = (1.f - z) * n + z * hp0;
        }
        {
            float r = sigmoidf_(gr1[j] + ar1 + br);
            float z = sigmoidf_(gr1[H + j] + az1 + bz);
            float n = tanhf(gr1[2 * H + j] + r * (an1 + bn));
            hout[(size_t)b1 * H + j] = (1.f - z) * n + z * hp1;
        }
        grid_sync();
    }
}

// ================= decoder phase kernels =================

// GRU cell (FMA2): grid 128 blocks x 256 thr; block owns 8 cols; thread = (c 0..3 pairing
// cols jb+c & jb+c+4, batch b). 6 paired chains, each lane = whole k-ascending chain.
__global__ __launch_bounds__(256) void dec_gru(
    const float* __restrict__ x, int xstride, int use_tok, int s,
    const float* __restrict__ Wih, const float* __restrict__ bih,
    const float* __restrict__ hin,
    const float* __restrict__ Whh, const float* __restrict__ bhh,
    float* __restrict__ hout, float* __restrict__ cat_aux)
{
    __shared__ float xs[64 * XS_PITCH];
    __shared__ float hs[64 * XS_PITCH];
    __shared__ __align__(16) ULL wi2[12 * 66];
    __shared__ __align__(16) ULL wh2[12 * 66];
    __shared__ int toks[B];
    const int tid = threadIdx.x;
    const int c = tid & 3, b = tid >> 2;
    const int jb = blockIdx.x * 8;
    const int j0 = jb + c, j1 = jb + c + 4;

    if (use_tok && tid < B)
        toks[tid] = (s == 0) ? 0 : (V - 1 - (int)(g_keys[tid] & 0x7FFFULL));
    __syncthreads();

    ULL air = 0ULL, aiz = 0ULL, ain = 0ULL, ahr = 0ULL, ahz = 0ULL, ahn = 0ULL;

    for (int k0 = 0; k0 < H; k0 += 64) {
        for (int i = tid; i < 1024; i += 256) {
            int bb = i >> 4, kg = i & 15;
            const float* xr = use_tok ? (x + (size_t)toks[bb] * xstride)
                                      : (x + (size_t)bb * xstride);
            *(float4*)(xs + bb * XS_PITCH + kg * 4) = *(const float4*)(xr + k0 + kg * 4);
            *(float4*)(hs + bb * XS_PITCH + kg * 4) =
                *(const float4*)(hin + (size_t)bb * H + k0 + kg * 4);
        }
        for (int i = tid; i < 768; i += 256) {
            int slot = i >> 6, kk = i & 63;
            int g = slot >> 2, p = slot & 3;
            ((float2*)wi2)[slot * 66 + kk] = make_float2(
                Wih[(size_t)(g * H + jb + p) * H + k0 + kk],
                Wih[(size_t)(g * H + jb + 4 + p) * H + k0 + kk]);
            ((float2*)wh2)[slot * 66 + kk] = make_float2(
                Whh[(size_t)(g * H + jb + p) * H + k0 + kk],
                Whh[(size_t)(g * H + jb + 4 + p) * H + k0 + kk]);
        }
        __syncthreads();
#pragma unroll 4
        for (int kk = 0; kk < 64; kk += 2) {
            float2 xv = *(const float2*)(xs + b * XS_PITCH + kk);
            float2 hv = *(const float2*)(hs + b * XS_PITCH + kk);
            ULL xa = splat2(xv.x), xb = splat2(xv.y);
            ULL ha = splat2(hv.x), hb = splat2(hv.y);
            ulonglong2 wir = *(const ulonglong2*)(wi2 + c * 66 + kk);
            ulonglong2 wiz = *(const ulonglong2*)(wi2 + (4 + c) * 66 + kk);
            ulonglong2 win = *(const ulonglong2*)(wi2 + (8 + c) * 66 + kk);
            ulonglong2 whr = *(const ulonglong2*)(wh2 + c * 66 + kk);
            ulonglong2 whz = *(const ulonglong2*)(wh2 + (4 + c) * 66 + kk);
            ulonglong2 whn = *(const ulonglong2*)(wh2 + (8 + c) * 66 + kk);
            fma2(air, wir.x, xa); fma2(air, wir.y, xb);
            fma2(aiz, wiz.x, xa); fma2(aiz, wiz.y, xb);
            fma2(ain, win.x, xa); fma2(ain, win.y, xb);
            fma2(ahr, whr.x, ha); fma2(ahr, whr.y, hb);
            fma2(ahz, whz.x, ha); fma2(ahz, whz.y, hb);
            fma2(ahn, whn.x, ha); fma2(ahn, whn.y, hb);
        }
        __syncthreads();
    }
    float2 vir = unpack2(air), viz = unpack2(aiz), vin = unpack2(ain);
    float2 vhr = unpack2(ahr), vhz = unpack2(ahz), vhn = unpack2(ahn);
    {
        float hp = hin[(size_t)b * H + j0];
        float r = sigmoidf_((vir.x + bih[j0]) + (vhr.x + bhh[j0]));
        float z = sigmoidf_((viz.x + bih[H + j0]) + (vhz.x + bhh[H + j0]));
        float n = tanhf((vin.x + bih[2 * H + j0]) + r * (vhn.x + bhh[2 * H + j0]));
        float h = (1.f - z) * n + z * hp;
        hout[(size_t)b * H + j0] = h;
        if (cat_aux) cat_aux[(size_t)b * 2 * H + H + j0] = h;
    }
    {
        float hp = hin[(size_t)b * H + j1];
        float r = sigmoidf_((vir.y + bih[j1]) + (vhr.y + bhh[j1]));
        float z = sigmoidf_((viz.y + bih[H + j1]) + (vhz.y + bhh[H + j1]));
        float n = tanhf((vin.y + bih[2 * H + j1]) + r * (vhn.y + bhh[2 * H + j1]));
        float h = (1.f - z) * n + z * hp;
        hout[(size_t)b * H + j1] = h;
        if (cat_aux) cat_aux[(size_t)b * 2 * H + H + j1] = h;
    }
}

// Linear: Y[b][jb+c] = X[b] . Wt[jb+c] + bias; grid 256 x 256; 1 whole chain / thread.
__global__ __launch_bounds__(256) void lin_kernel(
    const float* __restrict__ Wt, int wstride, const float* __restrict__ bias,
    const float* __restrict__ X, int xstride, int K, float* __restrict__ Y,
    int reset_keys)
{
    __shared__ float xs[64 * XS_PITCH];
    __shared__ float ws[4 * XS_PITCH];
    const int tid = threadIdx.x;
    const int c = tid & 3, b = tid >> 2;
    const int jb = blockIdx.x * 4;
    if (reset_keys && blockIdx.x == 0 && tid < B) g_keys[tid] = 0ULL;

    float a = 0.f;
    for (int k0 = 0; k0 < K; k0 += 64) {
        for (int i = tid; i < 1024; i += 256) {
            int bb = i >> 4, kg = i & 15;
            *(float4*)(xs + bb * XS_PITCH + kg * 4) =
                *(const float4*)(X + (size_t)bb * xstride + k0 + kg * 4);
        }
        if (tid < 64) {
            int r = tid >> 4, kg = tid & 15;
            *(float4*)(ws + r * XS_PITCH + kg * 4) =
                *(const float4*)(Wt + (size_t)(jb + r) * wstride + k0 + kg * 4);
        }
        __syncthreads();
#pragma unroll
        for (int kk = 0; kk < 64; kk += 4) {
            float4 xv = *(const float4*)(xs + b * XS_PITCH + kk);
            float4 wv = *(const float4*)(ws + c * XS_PITCH + kk);
            a = fmaf(wv.x, xv.x, a); a = fmaf(wv.y, xv.y, a);
            a = fmaf(wv.z, xv.z, a); a = fmaf(wv.w, xv.w, a);
        }
        __syncthreads();
    }
    Y[(size_t)b * H + jb + c] = a + bias[jb + c];
}

// attention: grid 64 blocks x 1024 threads (math identical)
__global__ __launch_bounds__(1024) void attn_kernel(
    const float* __restrict__ q, const float* __restrict__ enc,
    float* __restrict__ cat, float* __restrict__ attn_out, int s)
{
    __shared__ float qs[H];
    __shared__ float wv[TIN];
    __shared__ float red[256];
    const int b = blockIdx.x, tid = threadIdx.x;
    qs[tid] = q[(size_t)b * H + tid];
    __syncthreads();
    const int warp = tid >> 5, lane = tid & 31;
    for (int t = warp; t < TIN; t += 32) {
        const float* e = enc + (size_t)(t * B + b) * H;
        float sacc = 0.f;
#pragma unroll 4
        for (int k = lane; k < H; k += 32) sacc = fmaf(qs[k], e[k], sacc);
        for (int o = 16; o; o >>= 1) sacc += __shfl_xor_sync(0xffffffffu, sacc, o);
        if (!lane) wv[t] = sacc;
    }
    __syncthreads();
    float v = 0.f, ev = 0.f;
    if (tid < 256) { v = wv[tid]; red[tid] = v; }
    __syncthreads();
    for (int st = 128; st; st >>= 1) { if (tid < st) red[tid] = fmaxf(red[tid], red[tid + st]); __syncthreads(); }
    float mx = red[0]; __syncthreads();
    if (tid < 256) { ev = expf(v - mx); red[tid] = ev; }
    __syncthreads();
    for (int st = 128; st; st >>= 1) { if (tid < st) red[tid] += red[tid + st]; __syncthreads(); }
    if (tid < 256) {
        float aw = ev / red[0];
        wv[tid] = aw;
        attn_out[((size_t)b * TIN + tid) * TGT + s] = aw;
    }
    __syncthreads();
    {
        int k = tid;
        float sacc = 0.f;
        for (int t = 0; t < TIN; t++) sacc = fmaf(wv[t], enc[(size_t)(t * B + b) * H + k], sacc);
        cat[(size_t)b * 2 * H + k] = sacc;
    }
}

// fc + fused argmax (FMA2): grid 500 x 256; tile 64m x 64n; same columns/values as scalar.
__global__ __launch_bounds__(256) void fc_argmax(
    const float* __restrict__ A, const float* __restrict__ Wfc,
    const float* __restrict__ bfc, float* __restrict__ out, int s)
{
    __shared__ __align__(16) ULL As2[64 * 33];
    __shared__ __align__(16) ULL Ws2[32 * 33];
    __shared__ ULL skeys[B];
    const int tid = threadIdx.x;
    const int tx = tid & 15, ty = tid >> 4;
    const int n0 = blockIdx.x * 64;
    if (tid < B) skeys[tid] = 0ULL;

    ULL acc[4][2];
#pragma unroll
    for (int i = 0; i < 4; i++)
#pragma unroll
        for (int q = 0; q < 2; q++) acc[i][q] = 0ULL;

    for (int k0 = 0; k0 < H; k0 += 32) {
        for (int i = tid; i < 2048; i += 256) {
            int m = i >> 5, k = i & 31;
            float v = A[(size_t)m * H + k0 + k];
            ((float2*)As2)[m * 33 + k] = make_float2(v, v);
        }
        for (int i = tid; i < 1024; i += 256) {
            int pc = i >> 5, k = i & 31;
            int n_lo = n0 + (pc >> 4) * 32 + (pc & 15);
            ((float2*)Ws2)[pc * 33 + k] = make_float2(
                Wfc[(size_t)n_lo * H + k0 + k], Wfc[(size_t)(n_lo + 16) * H + k0 + k]);
        }
        __syncthreads();
#pragma unroll 8
        for (int k = 0; k < 32; k++) {
            ULL a0 = As2[ty * 33 + k], a1 = As2[(ty + 16) * 33 + k];
            ULL a2 = As2[(ty + 32) * 33 + k], a3 = As2[(ty + 48) * 33 + k];
            ULL w0 = Ws2[tx * 33 + k], w1 = Ws2[(16 + tx) * 33 + k];
            fma2(acc[0][0], w0, a0); fma2(acc[0][1], w1, a0);
            fma2(acc[1][0], w0, a1); fma2(acc[1][1], w1, a1);
            fma2(acc[2][0], w0, a2); fma2(acc[2][1], w1, a2);
            fma2(acc[3][0], w0, a3); fma2(acc[3][1], w1, a3);
        }
        __syncthreads();
    }
#pragma unroll
    for (int i = 0; i < 4; i++) {
        int m = ty + 16 * i;
        ULL rowmax = 0ULL;
#pragma unroll
        for (int q = 0; q < 2; q++) {
            float2 v = unpack2(acc[i][q]);
            int n_lo = n0 + q * 32 + tx;
            float v0 = v.x + bfc[n_lo];
            float v1 = v.y + bfc[n_lo + 16];
            out[((size_t)m * TGT + s) * V + n_lo]      = v0;
            out[((size_t)m * TGT + s) * V + n_lo + 16] = v1;
            ULL key0 = ((ULL)ord32(v0) << 15) | (ULL)(V - 1 - n_lo);
            ULL key1 = ((ULL)ord32(v1) << 15) | (ULL)(V - 1 - (n_lo + 16));
            if (key0 > rowmax) rowmax = key0;
            if (key1 > rowmax) rowmax = key1;
        }
        atomicMax(&skeys[m], rowmax);
    }
    __syncthreads();
    if (tid < B) atomicMax(&g_keys[tid], skeys[tid]);
}

// ================== host orchestration ==================
extern "C" void kernel_launch(void* const* d_in, const int* in_sizes, int n_in,
                              void* d_out_, int out_size) {
    const float* x      = (const float*)d_in[0];
    const float* embed  = (const float*)d_in[1];
    const float* eWih0  = (const float*)d_in[2];
    const float* eWhh0  = (const float*)d_in[3];
    const float* ebih0  = (const float*)d_in[4];
    const float* ebhh0  = (const float*)d_in[5];
    const float* eWih1  = (const float*)d_in[6];
    const float* eWhh1  = (const float*)d_in[7];
    const float* ebih1  = (const float*)d_in[8];
    const float* ebhh1  = (const float*)d_in[9];
    const float* dWih0  = (const float*)d_in[10];
    const float* dWhh0  = (const float*)d_in[11];
    const float* dbih0  = (const float*)d_in[12];
    const float* dbhh0  = (const float*)d_in[13];
    const float* dWih1  = (const float*)d_in[14];
    const float* dWhh1  = (const float*)d_in[15];
    const float* dbih1  = (const float*)d_in[16];
    const float* dbhh1  = (const float*)d_in[17];
    const float* Wq     = (const float*)d_in[18];
    const float* bq     = (const float*)d_in[19];
    const float* Wc     = (const float*)d_in[20];
    const float* bc     = (const float*)d_in[21];
    const float* Wfc    = (const float*)d_in[22];
    const float* bfc    = (const float*)d_in[23];
    float* out = (float*)d_out_;

    const size_t HID_OFF  = (size_t)B * TGT * V;
    const size_t ATTN_OFF = HID_OFF + (size_t)2 * BH;

    float *gi0, *gi1, *h0seq, *enc, *dh0, *dh1, *q, *cat, *comb;
    cudaGetSymbolAddress((void**)&gi0,   g_gi0);
    cudaGetSymbolAddress((void**)&gi1,   g_gi1);
    cudaGetSymbolAddress((void**)&h0seq, g_h0seq);
    cudaGetSymbolAddress((void**)&enc,   g_enc);
    cudaGetSymbolAddress((void**)&dh0,   g_dh0);
    cudaGetSymbolAddress((void**)&dh1,   g_dh1);
    cudaGetSymbolAddress((void**)&q,     g_q);
    cudaGetSymbolAddress((void**)&cat,   g_cat);
    cudaGetSymbolAddress((void**)&comb,  g_comb);

    const int ENC_SMEM = (24 * WS_PITCH + 64 * XS_PITCH) * (int)sizeof(float);
    cudaFuncSetAttribute(enc_recur_kernel, cudaFuncAttributeMaxDynamicSharedMemorySize, ENC_SMEM);

    // ---- encoder ----
    gemm2_tn<<<dim3(H3/128, (B*TIN)/64), 256>>>(x, eWih0, ebih0, gi0, F, F, F, H3);
    enc_recur_kernel<<<128, 256, ENC_SMEM>>>(
        gi0, (long long)H3, (long long)TIN * H3, eWhh0, ebhh0, h0seq);
    gemm2_tn<<<dim3(H3/128, (B*TIN)/64), 256>>>(h0seq, eWih1, ebih1, gi1, H, H, H, H3);
    enc_recur_kernel<<<128, 256, ENC_SMEM>>>(
        gi1, (long long)B * H3, (long long)H3, eWhh1, ebhh1, enc);

    // ---- decoder: 6 kernels per step ----
    for (int s = 0; s < TGT; s++) {
        const float* h0in = s ? (dh0 + (size_t)((s - 1) & 1) * BH) : (h0seq + (size_t)(TIN - 1) * BH);
        const float* h1in = s ? (dh1 + (size_t)((s - 1) & 1) * BH) : (enc + (size_t)(TIN - 1) * BH);
        float* h0out = dh0 + (size_t)(s & 1) * BH;
        float* h1out = dh1 + (size_t)(s & 1) * BH;

        dec_gru<<<128, 256>>>(embed, H, 1, s, dWih0, dbih0, h0in, dWhh0, dbhh0, h0out, nullptr);
        dec_gru<<<128, 256>>>(h0out, H, 0, s, dWih1, dbih1, h1in, dWhh1, dbhh1, h1out, cat);
        lin_kernel<<<256, 256>>>(Wq, H, bq, h1out, H, H, q, 0);
        attn_kernel<<<B, 1024>>>(q, enc, cat, out + ATTN_OFF, s);
        lin_kernel<<<256, 256>>>(Wc, 2 * H, bc, cat, 2 * H, 2 * H, comb, 1);  // also resets g_keys
        fc_argmax<<<V / 64, 256>>>(comb, Wfc, bfc, out, s);
    }

    // ---- final hidden [2,B,H]: decoder (h0,h1) after step TGT-1 (parity 1) ----
    cudaMemcpyAsync(out + HID_OFF,      dh0 + BH, (size_t)BH * sizeof(float), cudaMemcpyDeviceToDevice);
    cudaMemcpyAsync(out + HID_OFF + BH, dh1 + BH, (size_t)BH * sizeof(float), cudaMemcpyDeviceToDevice);
}

// round 8
// speedup vs baseline: 1.1075x; 1.1075x over previous
#include <cuda_runtime.h>
#include <cfloat>
#include <cstddef>

#define B 64
#define TIN 256
#define F 64
#define H 1024
#define H3 3072
#define TGT 64
#define V 32000
#define BH (B*H)

typedef unsigned long long ULL;
typedef unsigned int uint;

__device__ float g_gi0[(size_t)TIN * B * H3];
__device__ float g_gi1[(size_t)TIN * B * H3];
__device__ float g_h0seq[(size_t)TIN * BH];
__device__ float g_enc[(size_t)TIN * BH];
__device__ float g_dh0[2 * BH];
__device__ float g_dh1[2 * BH];
__device__ float g_q[BH];
__device__ float g_cat[B * 2 * H];
__device__ float g_comb[BH];
__device__ ULL   g_keys[B];
__device__ unsigned long long g_bar64;   // encoder-only grid barrier

__device__ __forceinline__ void grid_sync() {
    __syncthreads();
    if (threadIdx.x == 0) {
        __threadfence();
        unsigned long long old = atomicAdd(&g_bar64, 1ULL);
        unsigned gen = (unsigned)(old >> 32);
        if ((unsigned)old == gridDim.x - 1) {
            atomicAdd(&g_bar64, (1ULL << 32) - (unsigned long long)gridDim.x);
        } else {
            while ((unsigned)((*(volatile unsigned long long*)&g_bar64) >> 32) == gen) { }
        }
        __threadfence();
    }
    __syncthreads();
}

__device__ __forceinline__ float sigmoidf_(float x) { return 1.f / (1.f + expf(-x)); }
__device__ __forceinline__ void fma2(ULL& d, ULL a, ULL b) {
    asm("fma.rn.f32x2 %0, %1, %2, %0;" : "+l"(d) : "l"(a), "l"(b));
}
__device__ __forceinline__ float2 unpack2(ULL v) {
    float2 r; asm("mov.b64 {%0, %1}, %2;" : "=f"(r.x), "=f"(r.y) : "l"(v)); return r;
}
// total-order float key (matches '>' for non-NaN); monotone in value
__device__ __forceinline__ uint ord32(float f) {
    uint u = __float_as_uint(f);
    return u ^ ((u >> 31) ? 0xFFFFFFFFu : 0x80000000u);
}

// ============ FMA2 GEMM (bitwise-proven): C = A @ W^T + bias, tile 64x128 ============
__global__ __launch_bounds__(256) void gemm2_tn(
    const float* __restrict__ A, const float* __restrict__ W,
    const float* __restrict__ bias, float* __restrict__ C,
    int K, int lda, int ldw, int ldc)
{
    __shared__ __align__(16) ULL smu2[2 * 64 * 33];
    ULL* As2 = smu2;
    ULL* Ws2 = smu2 + 64 * 33;
    const int tid = threadIdx.x;
    const int tx = tid & 15, ty = tid >> 4;
    const int m0 = blockIdx.y * 64, n0 = blockIdx.x * 128;

    ULL acc[4][4];
#pragma unroll
    for (int r = 0; r < 4; r++)
#pragma unroll
        for (int q = 0; q < 4; q++) acc[r][q] = 0ULL;

    for (int k0 = 0; k0 < K; k0 += 32) {
        for (int i = tid; i < 2048; i += 256) {
            int m = i >> 5, k = i & 31;
            float v = A[(size_t)(m0 + m) * lda + k0 + k];
            ((float2*)As2)[m * 33 + k] = make_float2(v, v);
        }
        for (int i = tid; i < 2048; i += 256) {
            int pc = i >> 5, k = i & 31;
            int n_lo = n0 + (pc >> 4) * 32 + (pc & 15);
            ((float2*)Ws2)[pc * 33 + k] = make_float2(
                W[(size_t)n_lo * ldw + k0 + k], W[(size_t)(n_lo + 16) * ldw + k0 + k]);
        }
        __syncthreads();
#pragma unroll 8
        for (int k = 0; k < 32; k++) {
            ULL a0 = As2[ty * 33 + k], a1 = As2[(ty + 16) * 33 + k];
            ULL a2 = As2[(ty + 32) * 33 + k], a3 = As2[(ty + 48) * 33 + k];
            ULL w0 = Ws2[tx * 33 + k], w1 = Ws2[(16 + tx) * 33 + k];
            ULL w2 = Ws2[(32 + tx) * 33 + k], w3 = Ws2[(48 + tx) * 33 + k];
            fma2(acc[0][0], w0, a0); fma2(acc[0][1], w1, a0); fma2(acc[0][2], w2, a0); fma2(acc[0][3], w3, a0);
            fma2(acc[1][0], w0, a1); fma2(acc[1][1], w1, a1); fma2(acc[1][2], w2, a1); fma2(acc[1][3], w3, a1);
            fma2(acc[2][0], w0, a2); fma2(acc[2][1], w1, a2); fma2(acc[2][2], w2, a2); fma2(acc[2][3], w3, a2);
            fma2(acc[3][0], w0, a3); fma2(acc[3][1], w1, a3); fma2(acc[3][2], w2, a3); fma2(acc[3][3], w3, a3);
        }
        __syncthreads();
    }
#pragma unroll
    for (int r = 0; r < 4; r++) {
        int m = m0 + ty + 16 * r;
#pragma unroll
        for (int q = 0; q < 4; q++) {
            float2 v = unpack2(acc[r][q]);
            int n_lo = n0 + q * 32 + tx;
            C[(size_t)m * ldc + n_lo]      = v.x + bias[n_lo];
            C[(size_t)m * ldc + n_lo + 16] = v.y + bias[n_lo + 16];
        }
    }
}

// ============ persistent encoder recurrence — unchanged (proven) ============
#define WS_PITCH 1028
#define XS_PITCH 68
__global__ __launch_bounds__(256, 1) void enc_recur_kernel(
    const float* __restrict__ gi, long long gi_t_stride, long long gi_b_stride,
    const float* __restrict__ Whh, const float* __restrict__ bhh,
    float* __restrict__ hseq)
{
    extern __shared__ float sm[];
    float* ws = sm;
    float* xs = sm + 24 * WS_PITCH;

    const int tid = threadIdx.x;
    const int c = tid & 7, bq = tid >> 3;
    const int jb = blockIdx.x * 8;
    const int b0 = 2 * bq, b1 = b0 + 1;
    const int j = jb + c;

    for (int i = tid; i < 24 * 256; i += 256) {
        int r = i >> 8, kg = i & 255;
        int wr = (r >> 3) * H + jb + (r & 7);
        *(float4*)(ws + r * WS_PITCH + kg * 4) =
            *(const float4*)(Whh + (size_t)wr * H + kg * 4);
    }
    const float br = bhh[j], bz = bhh[H + j], bn = bhh[2 * H + j];
    __syncthreads();

    for (int t = 0; t < TIN; t++) {
        float ar0 = 0.f, ar1 = 0.f, az0 = 0.f, az1 = 0.f, an0 = 0.f, an1 = 0.f;
        const float* hprev = hseq + (size_t)(t - 1) * BH;
        if (t > 0) {
            for (int k0 = 0; k0 < H; k0 += 64) {
                for (int i = tid; i < 1024; i += 256) {
                    int b = i >> 4, kg = i & 15;
                    *(float4*)(xs + b * XS_PITCH + kg * 4) =
                        *(const float4*)(hprev + (size_t)b * H + k0 + kg * 4);
                }
                __syncthreads();
#pragma unroll
                for (int kk = 0; kk < 64; kk += 4) {
                    float4 x0 = *(const float4*)(xs + b0 * XS_PITCH + kk);
                    float4 x1 = *(const float4*)(xs + b1 * XS_PITCH + kk);
                    float4 w0 = *(const float4*)(ws + c * WS_PITCH + k0 + kk);
                    float4 w1 = *(const float4*)(ws + (8 + c) * WS_PITCH + k0 + kk);
                    float4 w2 = *(const float4*)(ws + (16 + c) * WS_PITCH + k0 + kk);
                    ar0 = fmaf(w0.x, x0.x, ar0); ar0 = fmaf(w0.y, x0.y, ar0);
                    ar0 = fmaf(w0.z, x0.z, ar0); ar0 = fmaf(w0.w, x0.w, ar0);
                    ar1 = fmaf(w0.x, x1.x, ar1); ar1 = fmaf(w0.y, x1.y, ar1);
                    ar1 = fmaf(w0.z, x1.z, ar1); ar1 = fmaf(w0.w, x1.w, ar1);
                    az0 = fmaf(w1.x, x0.x, az0); az0 = fmaf(w1.y, x0.y, az0);
                    az0 = fmaf(w1.z, x0.z, az0); az0 = fmaf(w1.w, x0.w, az0);
                    az1 = fmaf(w1.x, x1.x, az1); az1 = fmaf(w1.y, x1.y, az1);
                    az1 = fmaf(w1.z, x1.z, az1); az1 = fmaf(w1.w, x1.w, az1);
                    an0 = fmaf(w2.x, x0.x, an0); an0 = fmaf(w2.y, x0.y, an0);
                    an0 = fmaf(w2.z, x0.z, an0); an0 = fmaf(w2.w, x0.w, an0);
                    an1 = fmaf(w2.x, x1.x, an1); an1 = fmaf(w2.y, x1.y, an1);
                    an1 = fmaf(w2.z, x1.z, an1); an1 = fmaf(w2.w, x1.w, an1);
                }
                __syncthreads();
            }
        }
        const float* gr0 = gi + (size_t)b0 * gi_b_stride + (size_t)t * gi_t_stride;
        const float* gr1 = gi + (size_t)b1 * gi_b_stride + (size_t)t * gi_t_stride;
        float* hout = hseq + (size_t)t * BH;
        float hp0 = (t > 0) ? hprev[(size_t)b0 * H + j] : 0.f;
        float hp1 = (t > 0) ? hprev[(size_t)b1 * H + j] : 0.f;
        {
            float r = sigmoidf_(gr0[j] + ar0 + br);
            float z = sigmoidf_(gr0[H + j] + az0 + bz);
            float n = tanhf(gr0[2 * H + j] + r * (an0 + bn));
            hout[(size_t)b0 * H + j] = (1.f - z) * n + z * hp0;
        }
        {
            float r = sigmoidf_(gr1[j] + ar1 + br);
            float z = sigmoidf_(gr1[H + j] + az1 + bz);
            float n = tanhf(gr1[2 * H + j] + r * (an1 + bn));
            hout[(size_t)b1 * H + j] = (1.f - z) * n + z * hp1;
        }
        grid_sync();
    }
}

// ================= decoder phase kernels (R6 versions, proven 58.6ms) =================

// GRU cell: grid 256 blocks x 256 thr; block owns 4 cols; thread = (col c, batch b);
// 6 whole k-ascending chains per thread -> bitwise-identical epilogue.
__global__ __launch_bounds__(256) void dec_gru(
    const float* __restrict__ x, int xstride, int use_tok, int s,
    const float* __restrict__ Wih, const float* __restrict__ bih,
    const float* __restrict__ hin,
    const float* __restrict__ Whh, const float* __restrict__ bhh,
    float* __restrict__ hout, float* __restrict__ cat_aux)
{
    __shared__ float xs[64 * XS_PITCH];
    __shared__ float hs[64 * XS_PITCH];
    __shared__ float wi[12 * XS_PITCH];
    __shared__ float wh[12 * XS_PITCH];
    __shared__ int toks[B];
    const int tid = threadIdx.x;
    const int c = tid & 3, b = tid >> 2;
    const int jb = blockIdx.x * 4;
    const int j = jb + c;

    if (use_tok && tid < B)
        toks[tid] = (s == 0) ? 0 : (V - 1 - (int)(g_keys[tid] & 0x7FFFULL));
    __syncthreads();

    float air = 0.f, aiz = 0.f, ain = 0.f, ahr = 0.f, ahz = 0.f, ahn = 0.f;

    for (int k0 = 0; k0 < H; k0 += 64) {
        for (int i = tid; i < 1024; i += 256) {
            int bb = i >> 4, kg = i & 15;
            const float* xr = use_tok ? (x + (size_t)toks[bb] * xstride)
                                      : (x + (size_t)bb * xstride);
            *(float4*)(xs + bb * XS_PITCH + kg * 4) = *(const float4*)(xr + k0 + kg * 4);
            *(float4*)(hs + bb * XS_PITCH + kg * 4) =
                *(const float4*)(hin + (size_t)bb * H + k0 + kg * 4);
        }
        if (tid < 192) {
            int r = tid >> 4, kg = tid & 15;
            int wr = (r >> 2) * H + jb + (r & 3);
            *(float4*)(wi + r * XS_PITCH + kg * 4) = *(const float4*)(Wih + (size_t)wr * H + k0 + kg * 4);
            *(float4*)(wh + r * XS_PITCH + kg * 4) = *(const float4*)(Whh + (size_t)wr * H + k0 + kg * 4);
        }
        __syncthreads();
#pragma unroll
        for (int kk = 0; kk < 64; kk += 4) {
            float4 xv = *(const float4*)(xs + b * XS_PITCH + kk);
            float4 hv = *(const float4*)(hs + b * XS_PITCH + kk);
            float4 wir = *(const float4*)(wi + c * XS_PITCH + kk);
            float4 wiz = *(const float4*)(wi + (4 + c) * XS_PITCH + kk);
            float4 win = *(const float4*)(wi + (8 + c) * XS_PITCH + kk);
            float4 whr = *(const float4*)(wh + c * XS_PITCH + kk);
            float4 whz = *(const float4*)(wh + (4 + c) * XS_PITCH + kk);
            float4 whn = *(const float4*)(wh + (8 + c) * XS_PITCH + kk);
            air = fmaf(wir.x, xv.x, air); air = fmaf(wir.y, xv.y, air);
            air = fmaf(wir.z, xv.z, air); air = fmaf(wir.w, xv.w, air);
            aiz = fmaf(wiz.x, xv.x, aiz); aiz = fmaf(wiz.y, xv.y, aiz);
            aiz = fmaf(wiz.z, xv.z, aiz); aiz = fmaf(wiz.w, xv.w, aiz);
            ain = fmaf(win.x, xv.x, ain); ain = fmaf(win.y, xv.y, ain);
            ain = fmaf(win.z, xv.z, ain); ain = fmaf(win.w, xv.w, ain);
            ahr = fmaf(whr.x, hv.x, ahr); ahr = fmaf(whr.y, hv.y, ahr);
            ahr = fmaf(whr.z, hv.z, ahr); ahr = fmaf(whr.w, hv.w, ahr);
            ahz = fmaf(whz.x, hv.x, ahz); ahz = fmaf(whz.y, hv.y, ahz);
            ahz = fmaf(whz.z, hv.z, ahz); ahz = fmaf(whz.w, hv.w, ahz);
            ahn = fmaf(whn.x, hv.x, ahn); ahn = fmaf(whn.y, hv.y, ahn);
            ahn = fmaf(whn.z, hv.z, ahn); ahn = fmaf(whn.w, hv.w, ahn);
        }
        __syncthreads();
    }
    float hp = hin[(size_t)b * H + j];
    float r = sigmoidf_((air + bih[j]) + (ahr + bhh[j]));
    float z = sigmoidf_((aiz + bih[H + j]) + (ahz + bhh[H + j]));
    float n = tanhf((ain + bih[2 * H + j]) + r * (ahn + bhh[2 * H + j]));
    float h = (1.f - z) * n + z * hp;
    hout[(size_t)b * H + j] = h;
    if (cat_aux) cat_aux[(size_t)b * 2 * H + H + j] = h;
}

// Linear: Y[b][jb+c] = X[b] . Wt[jb+c] + bias; grid 256 x 256; 1 whole chain / thread.
__global__ __launch_bounds__(256) void lin_kernel(
    const float* __restrict__ Wt, int wstride, const float* __restrict__ bias,
    const float* __restrict__ X, int xstride, int K, float* __restrict__ Y,
    int reset_keys)
{
    __shared__ float xs[64 * XS_PITCH];
    __shared__ float ws[4 * XS_PITCH];
    const int tid = threadIdx.x;
    const int c = tid & 3, b = tid >> 2;
    const int jb = blockIdx.x * 4;
    if (reset_keys && blockIdx.x == 0 && tid < B) g_keys[tid] = 0ULL;

    float a = 0.f;
    for (int k0 = 0; k0 < K; k0 += 64) {
        for (int i = tid; i < 1024; i += 256) {
            int bb = i >> 4, kg = i & 15;
            *(float4*)(xs + bb * XS_PITCH + kg * 4) =
                *(const float4*)(X + (size_t)bb * xstride + k0 + kg * 4);
        }
        if (tid < 64) {
            int r = tid >> 4, kg = tid & 15;
            *(float4*)(ws + r * XS_PITCH + kg * 4) =
                *(const float4*)(Wt + (size_t)(jb + r) * wstride + k0 + kg * 4);
        }
        __syncthreads();
#pragma unroll
        for (int kk = 0; kk < 64; kk += 4) {
            float4 xv = *(const float4*)(xs + b * XS_PITCH + kk);
            float4 wv = *(const float4*)(ws + c * XS_PITCH + kk);
            a = fmaf(wv.x, xv.x, a); a = fmaf(wv.y, xv.y, a);
            a = fmaf(wv.z, xv.z, a); a = fmaf(wv.w, xv.w, a);
        }
        __syncthreads();
    }
    Y[(size_t)b * H + jb + c] = a + bias[jb + c];
}

// attention: grid 64 blocks x 1024 threads (math identical)
__global__ __launch_bounds__(1024) void attn_kernel(
    const float* __restrict__ q, const float* __restrict__ enc,
    float* __restrict__ cat, float* __restrict__ attn_out, int s)
{
    __shared__ float qs[H];
    __shared__ float wv[TIN];
    __shared__ float red[256];
    const int b = blockIdx.x, tid = threadIdx.x;
    qs[tid] = q[(size_t)b * H + tid];
    __syncthreads();
    const int warp = tid >> 5, lane = tid & 31;
    for (int t = warp; t < TIN; t += 32) {
        const float* e = enc + (size_t)(t * B + b) * H;
        float sacc = 0.f;
#pragma unroll 4
        for (int k = lane; k < H; k += 32) sacc = fmaf(qs[k], e[k], sacc);
        for (int o = 16; o; o >>= 1) sacc += __shfl_xor_sync(0xffffffffu, sacc, o);
        if (!lane) wv[t] = sacc;
    }
    __syncthreads();
    float v = 0.f, ev = 0.f;
    if (tid < 256) { v = wv[tid]; red[tid] = v; }
    __syncthreads();
    for (int st = 128; st; st >>= 1) { if (tid < st) red[tid] = fmaxf(red[tid], red[tid + st]); __syncthreads(); }
    float mx = red[0]; __syncthreads();
    if (tid < 256) { ev = expf(v - mx); red[tid] = ev; }
    __syncthreads();
    for (int st = 128; st; st >>= 1) { if (tid < st) red[tid] += red[tid + st]; __syncthreads(); }
    if (tid < 256) {
        float aw = ev / red[0];
        wv[tid] = aw;
        attn_out[((size_t)b * TIN + tid) * TGT + s] = aw;
    }
    __syncthreads();
    {
        int k = tid;
        float sacc = 0.f;
        for (int t = 0; t < TIN; t++) sacc = fmaf(wv[t], enc[(size_t)(t * B + b) * H + k], sacc);
        cat[(size_t)b * 2 * H + k] = sacc;
    }
}

// fc + fused argmax, register-double-buffered: grid 500 x 256; tile 64m x 64n.
// thread (tx 0..15, ty 0..15) owns m = ty*4+{0..3}, n = n0+tx*4+{0..3}.
// Every output: single-accumulator k-ascending fmaf chain + bias -> bitwise == R6.
#define FCP 68   // smem pitch (floats), multiple of 4 for LDS.128
__global__ __launch_bounds__(256) void fc_argmax(
    const float* __restrict__ A, const float* __restrict__ Wfc,
    const float* __restrict__ bfc, float* __restrict__ out, int s)
{
    __shared__ __align__(16) float As[32 * FCP];   // [k][m]
    __shared__ __align__(16) float Ws[32 * FCP];   // [k][n]
    __shared__ ULL skeys[B];
    const int tid = threadIdx.x;
    const int tx = tid & 15, ty = tid >> 4;
    const int n0 = blockIdx.x * 64;
    if (tid < B) skeys[tid] = 0ULL;

    // prefetch mapping: f4 index i (0..511): row = i>>3 (0..63), kq = i&7 (k = kq*4..kq*4+3)
    const int prow = tid >> 3;            // rows 0..31 (it=0), 32..63 (it=1)
    const int pkq  = tid & 7;
    float4 pa[2], pw[2];
#pragma unroll
    for (int it = 0; it < 2; it++) {
        int row = prow + it * 32;
        pa[it] = *(const float4*)(A   + (size_t)row * H        + pkq * 4);
        pw[it] = *(const float4*)(Wfc + (size_t)(n0 + row) * H + pkq * 4);
    }

    float acc[4][4];
#pragma unroll
    for (int i = 0; i < 4; i++)
#pragma unroll
        for (int jj = 0; jj < 4; jj++) acc[i][jj] = 0.f;

    for (int c = 0; c < 32; c++) {
        __syncthreads();   // previous chunk's smem reads done
#pragma unroll
        for (int it = 0; it < 2; it++) {
            int row = prow + it * 32;
            As[(pkq * 4 + 0) * FCP + row] = pa[it].x;
            As[(pkq * 4 + 1) * FCP + row] = pa[it].y;
            As[(pkq * 4 + 2) * FCP + row] = pa[it].z;
            As[(pkq * 4 + 3) * FCP + row] = pa[it].w;
            Ws[(pkq * 4 + 0) * FCP + row] = pw[it].x;
            Ws[(pkq * 4 + 1) * FCP + row] = pw[it].y;
            Ws[(pkq * 4 + 2) * FCP + row] = pw[it].z;
            Ws[(pkq * 4 + 3) * FCP + row] = pw[it].w;
        }
        __syncthreads();
        if (c < 31) {
            int k0n = (c + 1) * 32;
#pragma unroll
            for (int it = 0; it < 2; it++) {
                int row = prow + it * 32;
                pa[it] = *(const float4*)(A   + (size_t)row * H        + k0n + pkq * 4);
                pw[it] = *(const float4*)(Wfc + (size_t)(n0 + row) * H + k0n + pkq * 4);
            }
        }
#pragma unroll
        for (int k = 0; k < 32; k++) {
            float4 av = *(const float4*)(As + k * FCP + ty * 4);
            float4 wv = *(const float4*)(Ws + k * FCP + tx * 4);
            acc[0][0] = fmaf(av.x, wv.x, acc[0][0]); acc[0][1] = fmaf(av.x, wv.y, acc[0][1]);
            acc[0][2] = fmaf(av.x, wv.z, acc[0][2]); acc[0][3] = fmaf(av.x, wv.w, acc[0][3]);
            acc[1][0] = fmaf(av.y, wv.x, acc[1][0]); acc[1][1] = fmaf(av.y, wv.y, acc[1][1]);
            acc[1][2] = fmaf(av.y, wv.z, acc[1][2]); acc[1][3] = fmaf(av.y, wv.w, acc[1][3]);
            acc[2][0] = fmaf(av.z, wv.x, acc[2][0]); acc[2][1] = fmaf(av.z, wv.y, acc[2][1]);
            acc[2][2] = fmaf(av.z, wv.z, acc[2][2]); acc[2][3] = fmaf(av.z, wv.w, acc[2][3]);
            acc[3][0] = fmaf(av.w, wv.x, acc[3][0]); acc[3][1] = fmaf(av.w, wv.y, acc[3][1]);
            acc[3][2] = fmaf(av.w, wv.z, acc[3][2]); acc[3][3] = fmaf(av.w, wv.w, acc[3][3]);
        }
    }
#pragma unroll
    for (int i = 0; i < 4; i++) {
        int m = ty * 4 + i;
        int nl = n0 + tx * 4;
        float4 vo;
        vo.x = acc[i][0] + bfc[nl];
        vo.y = acc[i][1] + bfc[nl + 1];
        vo.z = acc[i][2] + bfc[nl + 2];
        vo.w = acc[i][3] + bfc[nl + 3];
        *(float4*)(out + ((size_t)m * TGT + s) * V + nl) = vo;
        ULL rowmax = ((ULL)ord32(vo.x) << 15) | (ULL)(V - 1 - nl);
        ULL k1 = ((ULL)ord32(vo.y) << 15) | (ULL)(V - 1 - (nl + 1));
        ULL k2 = ((ULL)ord32(vo.z) << 15) | (ULL)(V - 1 - (nl + 2));
        ULL k3 = ((ULL)ord32(vo.w) << 15) | (ULL)(V - 1 - (nl + 3));
        if (k1 > rowmax) rowmax = k1;
        if (k2 > rowmax) rowmax = k2;
        if (k3 > rowmax) rowmax = k3;
        atomicMax(&skeys[m], rowmax);
    }
    __syncthreads();
    if (tid < B) atomicMax(&g_keys[tid], skeys[tid]);
}

// ================== host orchestration ==================
extern "C" void kernel_launch(void* const* d_in, const int* in_sizes, int n_in,
                              void* d_out_, int out_size) {
    const float* x      = (const float*)d_in[0];
    const float* embed  = (const float*)d_in[1];
    const float* eWih0  = (const float*)d_in[2];
    const float* eWhh0  = (const float*)d_in[3];
    const float* ebih0  = (const float*)d_in[4];
    const float* ebhh0  = (const float*)d_in[5];
    const float* eWih1  = (const float*)d_in[6];
    const float* eWhh1  = (const float*)d_in[7];
    const float* ebih1  = (const float*)d_in[8];
    const float* ebhh1  = (const float*)d_in[9];
    const float* dWih0  = (const float*)d_in[10];
    const float* dWhh0  = (const float*)d_in[11];
    const float* dbih0  = (const float*)d_in[12];
    const float* dbhh0  = (const float*)d_in[13];
    const float* dWih1  = (const float*)d_in[14];
    const float* dWhh1  = (const float*)d_in[15];
    const float* dbih1  = (const float*)d_in[16];
    const float* dbhh1  = (const float*)d_in[17];
    const float* Wq     = (const float*)d_in[18];
    const float* bq     = (const float*)d_in[19];
    const float* Wc     = (const float*)d_in[20];
    const float* bc     = (const float*)d_in[21];
    const float* Wfc    = (const float*)d_in[22];
    const float* bfc    = (const float*)d_in[23];
    float* out = (float*)d_out_;

    const size_t HID_OFF  = (size_t)B * TGT * V;
    const size_t ATTN_OFF = HID_OFF + (size_t)2 * BH;

    float *gi0, *gi1, *h0seq, *enc, *dh0, *dh1, *q, *cat, *comb;
    cudaGetSymbolAddress((void**)&gi0,   g_gi0);
    cudaGetSymbolAddress((void**)&gi1,   g_gi1);
    cudaGetSymbolAddress((void**)&h0seq, g_h0seq);
    cudaGetSymbolAddress((void**)&enc,   g_enc);
    cudaGetSymbolAddress((void**)&dh0,   g_dh0);
    cudaGetSymbolAddress((void**)&dh1,   g_dh1);
    cudaGetSymbolAddress((void**)&q,     g_q);
    cudaGetSymbolAddress((void**)&cat,   g_cat);
    cudaGetSymbolAddress((void**)&comb,  g_comb);

    const int ENC_SMEM = (24 * WS_PITCH + 64 * XS_PITCH) * (int)sizeof(float);
    cudaFuncSetAttribute(enc_recur_kernel, cudaFuncAttributeMaxDynamicSharedMemorySize, ENC_SMEM);

    // ---- encoder ----
    gemm2_tn<<<dim3(H3/128, (B*TIN)/64), 256>>>(x, eWih0, ebih0, gi0, F, F, F, H3);
    enc_recur_kernel<<<128, 256, ENC_SMEM>>>(
        gi0, (long long)H3, (long long)TIN * H3, eWhh0, ebhh0, h0seq);
    gemm2_tn<<<dim3(H3/128, (B*TIN)/64), 256>>>(h0seq, eWih1, ebih1, gi1, H, H, H, H3);
    enc_recur_kernel<<<128, 256, ENC_SMEM>>>(
        gi1, (long long)B * H3, (long long)H3, eWhh1, ebhh1, enc);

    // ---- decoder: 6 kernels per step ----
    for (int s = 0; s < TGT; s++) {
        const float* h0in = s ? (dh0 + (size_t)((s - 1) & 1) * BH) : (h0seq + (size_t)(TIN - 1) * BH);
        const float* h1in = s ? (dh1 + (size_t)((s - 1) & 1) * BH) : (enc + (size_t)(TIN - 1) * BH);
        float* h0out = dh0 + (size_t)(s & 1) * BH;
        float* h1out = dh1 + (size_t)(s & 1) * BH;

        dec_gru<<<256, 256>>>(embed, H, 1, s, dWih0, dbih0, h0in, dWhh0, dbhh0, h0out, nullptr);
        dec_gru<<<256, 256>>>(h0out, H, 0, s, dWih1, dbih1, h1in, dWhh1, dbhh1, h1out, cat);
        lin_kernel<<<256, 256>>>(Wq, H, bq, h1out, H, H, q, 0);
        attn_kernel<<<B, 1024>>>(q, enc, cat, out + ATTN_OFF, s);
        lin_kernel<<<256, 256>>>(Wc, 2 * H, bc, cat, 2 * H, 2 * H, comb, 1);  // also resets g_keys
        fc_argmax<<<V / 64, 256>>>(comb, Wfc, bfc, out, s);
    }

    // ---- final hidden [2,B,H]: decoder (h0,h1) after step TGT-1 (parity 1) ----
    cudaMemcpyAsync(out + HID_OFF,      dh0 + BH, (size_t)BH * sizeof(float), cudaMemcpyDeviceToDevice);
    cudaMemcpyAsync(out + HID_OFF + BH, dh1 + BH, (size_t)BH * sizeof(float), cudaMemcpyDeviceToDevice);
}

// round 9
// speedup vs baseline: 1.1128x; 1.0048x over previous
#include <cuda_runtime.h>
#include <cfloat>
#include <cstddef>

#define B 64
#define TIN 256
#define F 64
#define H 1024
#define H3 3072
#define TGT 64
#define V 32000
#define BH (B*H)

typedef unsigned long long ULL;
typedef unsigned int uint;

__device__ float g_gi0[(size_t)TIN * B * H3];
__device__ float g_gi1[(size_t)TIN * B * H3];
__device__ float g_h0seq[(size_t)TIN * BH];
__device__ float g_enc[(size_t)TIN * BH];
__device__ float g_dh0[2 * BH];
__device__ float g_dh1[2 * BH];
__device__ float g_q[BH];
__device__ float g_cat[B * 2 * H];
__device__ float g_comb[BH];
__device__ ULL   g_keys[B];
__device__ unsigned long long g_bar64;   // encoder-only grid barrier

__device__ __forceinline__ void grid_sync() {
    __syncthreads();
    if (threadIdx.x == 0) {
        __threadfence();
        unsigned long long old = atomicAdd(&g_bar64, 1ULL);
        unsigned gen = (unsigned)(old >> 32);
        if ((unsigned)old == gridDim.x - 1) {
            atomicAdd(&g_bar64, (1ULL << 32) - (unsigned long long)gridDim.x);
        } else {
            while ((unsigned)((*(volatile unsigned long long*)&g_bar64) >> 32) == gen) { }
        }
        __threadfence();
    }
    __syncthreads();
}

__device__ __forceinline__ float sigmoidf_(float x) { return 1.f / (1.f + expf(-x)); }
__device__ __forceinline__ void fma2(ULL& d, ULL a, ULL b) {
    asm("fma.rn.f32x2 %0, %1, %2, %0;" : "+l"(d) : "l"(a), "l"(b));
}
__device__ __forceinline__ float2 unpack2(ULL v) {
    float2 r; asm("mov.b64 {%0, %1}, %2;" : "=f"(r.x), "=f"(r.y) : "l"(v)); return r;
}
// total-order float key (matches '>' for non-NaN); monotone in value
__device__ __forceinline__ uint ord32(float f) {
    uint u = __float_as_uint(f);
    return u ^ ((u >> 31) ? 0xFFFFFFFFu : 0x80000000u);
}

// ============ FMA2 GEMM (bitwise-proven): C = A @ W^T + bias, tile 64x128 ============
__global__ __launch_bounds__(256) void gemm2_tn(
    const float* __restrict__ A, const float* __restrict__ W,
    const float* __restrict__ bias, float* __restrict__ C,
    int K, int lda, int ldw, int ldc)
{
    __shared__ __align__(16) ULL smu2[2 * 64 * 33];
    ULL* As2 = smu2;
    ULL* Ws2 = smu2 + 64 * 33;
    const int tid = threadIdx.x;
    const int tx = tid & 15, ty = tid >> 4;
    const int m0 = blockIdx.y * 64, n0 = blockIdx.x * 128;

    ULL acc[4][4];
#pragma unroll
    for (int r = 0; r < 4; r++)
#pragma unroll
        for (int q = 0; q < 4; q++) acc[r][q] = 0ULL;

    for (int k0 = 0; k0 < K; k0 += 32) {
        for (int i = tid; i < 2048; i += 256) {
            int m = i >> 5, k = i & 31;
            float v = A[(size_t)(m0 + m) * lda + k0 + k];
            ((float2*)As2)[m * 33 + k] = make_float2(v, v);
        }
        for (int i = tid; i < 2048; i += 256) {
            int pc = i >> 5, k = i & 31;
            int n_lo = n0 + (pc >> 4) * 32 + (pc & 15);
            ((float2*)Ws2)[pc * 33 + k] = make_float2(
                W[(size_t)n_lo * ldw + k0 + k], W[(size_t)(n_lo + 16) * ldw + k0 + k]);
        }
        __syncthreads();
#pragma unroll 8
        for (int k = 0; k < 32; k++) {
            ULL a0 = As2[ty * 33 + k], a1 = As2[(ty + 16) * 33 + k];
            ULL a2 = As2[(ty + 32) * 33 + k], a3 = As2[(ty + 48) * 33 + k];
            ULL w0 = Ws2[tx * 33 + k], w1 = Ws2[(16 + tx) * 33 + k];
            ULL w2 = Ws2[(32 + tx) * 33 + k], w3 = Ws2[(48 + tx) * 33 + k];
            fma2(acc[0][0], w0, a0); fma2(acc[0][1], w1, a0); fma2(acc[0][2], w2, a0); fma2(acc[0][3], w3, a0);
            fma2(acc[1][0], w0, a1); fma2(acc[1][1], w1, a1); fma2(acc[1][2], w2, a1); fma2(acc[1][3], w3, a1);
            fma2(acc[2][0], w0, a2); fma2(acc[2][1], w1, a2); fma2(acc[2][2], w2, a2); fma2(acc[2][3], w3, a2);
            fma2(acc[3][0], w0, a3); fma2(acc[3][1], w1, a3); fma2(acc[3][2], w2, a3); fma2(acc[3][3], w3, a3);
        }
        __syncthreads();
    }
#pragma unroll
    for (int r = 0; r < 4; r++) {
        int m = m0 + ty + 16 * r;
#pragma unroll
        for (int q = 0; q < 4; q++) {
            float2 v = unpack2(acc[r][q]);
            int n_lo = n0 + q * 32 + tx;
            C[(size_t)m * ldc + n_lo]      = v.x + bias[n_lo];
            C[(size_t)m * ldc + n_lo + 16] = v.y + bias[n_lo + 16];
        }
    }
}

// ============ persistent encoder recurrence — unchanged (proven) ============
#define WS_PITCH 1028
#define XS_PITCH 68
__global__ __launch_bounds__(256, 1) void enc_recur_kernel(
    const float* __restrict__ gi, long long gi_t_stride, long long gi_b_stride,
    const float* __restrict__ Whh, const float* __restrict__ bhh,
    float* __restrict__ hseq)
{
    extern __shared__ float sm[];
    float* ws = sm;
    float* xs = sm + 24 * WS_PITCH;

    const int tid = threadIdx.x;
    const int c = tid & 7, bq = tid >> 3;
    const int jb = blockIdx.x * 8;
    const int b0 = 2 * bq, b1 = b0 + 1;
    const int j = jb + c;

    for (int i = tid; i < 24 * 256; i += 256) {
        int r = i >> 8, kg = i & 255;
        int wr = (r >> 3) * H + jb + (r & 7);
        *(float4*)(ws + r * WS_PITCH + kg * 4) =
            *(const float4*)(Whh + (size_t)wr * H + kg * 4);
    }
    const float br = bhh[j], bz = bhh[H + j], bn = bhh[2 * H + j];
    __syncthreads();

    for (int t = 0; t < TIN; t++) {
        float ar0 = 0.f, ar1 = 0.f, az0 = 0.f, az1 = 0.f, an0 = 0.f, an1 = 0.f;
        const float* hprev = hseq + (size_t)(t - 1) * BH;
        if (t > 0) {
            for (int k0 = 0; k0 < H; k0 += 64) {
                for (int i = tid; i < 1024; i += 256) {
                    int b = i >> 4, kg = i & 15;
                    *(float4*)(xs + b * XS_PITCH + kg * 4) =
                        *(const float4*)(hprev + (size_t)b * H + k0 + kg * 4);
                }
                __syncthreads();
#pragma unroll
                for (int kk = 0; kk < 64; kk += 4) {
                    float4 x0 = *(const float4*)(xs + b0 * XS_PITCH + kk);
                    float4 x1 = *(const float4*)(xs + b1 * XS_PITCH + kk);
                    float4 w0 = *(const float4*)(ws + c * WS_PITCH + k0 + kk);
                    float4 w1 = *(const float4*)(ws + (8 + c) * WS_PITCH + k0 + kk);
                    float4 w2 = *(const float4*)(ws + (16 + c) * WS_PITCH + k0 + kk);
                    ar0 = fmaf(w0.x, x0.x, ar0); ar0 = fmaf(w0.y, x0.y, ar0);
                    ar0 = fmaf(w0.z, x0.z, ar0); ar0 = fmaf(w0.w, x0.w, ar0);
                    ar1 = fmaf(w0.x, x1.x, ar1); ar1 = fmaf(w0.y, x1.y, ar1);
                    ar1 = fmaf(w0.z, x1.z, ar1); ar1 = fmaf(w0.w, x1.w, ar1);
                    az0 = fmaf(w1.x, x0.x, az0); az0 = fmaf(w1.y, x0.y, az0);
                    az0 = fmaf(w1.z, x0.z, az0); az0 = fmaf(w1.w, x0.w, az0);
                    az1 = fmaf(w1.x, x1.x, az1); az1 = fmaf(w1.y, x1.y, az1);
                    az1 = fmaf(w1.z, x1.z, az1); az1 = fmaf(w1.w, x1.w, az1);
                    an0 = fmaf(w2.x, x0.x, an0); an0 = fmaf(w2.y, x0.y, an0);
                    an0 = fmaf(w2.z, x0.z, an0); an0 = fmaf(w2.w, x0.w, an0);
                    an1 = fmaf(w2.x, x1.x, an1); an1 = fmaf(w2.y, x1.y, an1);
                    an1 = fmaf(w2.z, x1.z, an1); an1 = fmaf(w2.w, x1.w, an1);
                }
                __syncthreads();
            }
        }
        const float* gr0 = gi + (size_t)b0 * gi_b_stride + (size_t)t * gi_t_stride;
        const float* gr1 = gi + (size_t)b1 * gi_b_stride + (size_t)t * gi_t_stride;
        float* hout = hseq + (size_t)t * BH;
        float hp0 = (t > 0) ? hprev[(size_t)b0 * H + j] : 0.f;
        float hp1 = (t > 0) ? hprev[(size_t)b1 * H + j] : 0.f;
        {
            float r = sigmoidf_(gr0[j] + ar0 + br);
            float z = sigmoidf_(gr0[H + j] + az0 + bz);
            float n = tanhf(gr0[2 * H + j] + r * (an0 + bn));
            hout[(size_t)b0 * H + j] = (1.f - z) * n + z * hp0;
        }
        {
            float r = sigmoidf_(gr1[j] + ar1 + br);
            float z = sigmoidf_(gr1[H + j] + az1 + bz);
            float n = tanhf(gr1[2 * H + j] + r * (an1 + bn));
            hout[(size_t)b1 * H + j] = (1.f - z) * n + z * hp1;
        }
        grid_sync();
    }
}

// ================= decoder phase kernels (R6 versions, proven 58.6ms) =================

// GRU cell: grid 256 blocks x 256 thr; block owns 4 cols; thread = (col c, batch b);
// 6 whole k-ascending chains per thread -> bitwise-identical epilogue.
__global__ __launch_bounds__(256) void dec_gru(
    const float* __restrict__ x, int xstride, int use_tok, int s,
    const float* __restrict__ Wih, const float* __restrict__ bih,
    const float* __restrict__ hin,
    const float* __restrict__ Whh, const float* __restrict__ bhh,
    float* __restrict__ hout, float* __restrict__ cat_aux)
{
    __shared__ float xs[64 * XS_PITCH];
    __shared__ float hs[64 * XS_PITCH];
    __shared__ float wi[12 * XS_PITCH];
    __shared__ float wh[12 * XS_PITCH];
    __shared__ int toks[B];
    const int tid = threadIdx.x;
    const int c = tid & 3, b = tid >> 2;
    const int jb = blockIdx.x * 4;
    const int j = jb + c;

    if (use_tok && tid < B)
        toks[tid] = (s == 0) ? 0 : (V - 1 - (int)(g_keys[tid] & 0x7FFFULL));
    __syncthreads();

    float air = 0.f, aiz = 0.f, ain = 0.f, ahr = 0.f, ahz = 0.f, ahn = 0.f;

    for (int k0 = 0; k0 < H; k0 += 64) {
        for (int i = tid; i < 1024; i += 256) {
            int bb = i >> 4, kg = i & 15;
            const float* xr = use_tok ? (x + (size_t)toks[bb] * xstride)
                                      : (x + (size_t)bb * xstride);
            *(float4*)(xs + bb * XS_PITCH + kg * 4) = *(const float4*)(xr + k0 + kg * 4);
            *(float4*)(hs + bb * XS_PITCH + kg * 4) =
                *(const float4*)(hin + (size_t)bb * H + k0 + kg * 4);
        }
        if (tid < 192) {
            int r = tid >> 4, kg = tid & 15;
            int wr = (r >> 2) * H + jb + (r & 3);
            *(float4*)(wi + r * XS_PITCH + kg * 4) = *(const float4*)(Wih + (size_t)wr * H + k0 + kg * 4);
            *(float4*)(wh + r * XS_PITCH + kg * 4) = *(const float4*)(Whh + (size_t)wr * H + k0 + kg * 4);
        }
        __syncthreads();
#pragma unroll
        for (int kk = 0; kk < 64; kk += 4) {
            float4 xv = *(const float4*)(xs + b * XS_PITCH + kk);
            float4 hv = *(const float4*)(hs + b * XS_PITCH + kk);
            float4 wir = *(const float4*)(wi + c * XS_PITCH + kk);
            float4 wiz = *(const float4*)(wi + (4 + c) * XS_PITCH + kk);
            float4 win = *(const float4*)(wi + (8 + c) * XS_PITCH + kk);
            float4 whr = *(const float4*)(wh + c * XS_PITCH + kk);
            float4 whz = *(const float4*)(wh + (4 + c) * XS_PITCH + kk);
            float4 whn = *(const float4*)(wh + (8 + c) * XS_PITCH + kk);
            air = fmaf(wir.x, xv.x, air); air = fmaf(wir.y, xv.y, air);
            air = fmaf(wir.z, xv.z, air); air = fmaf(wir.w, xv.w, air);
            aiz = fmaf(wiz.x, xv.x, aiz); aiz = fmaf(wiz.y, xv.y, aiz);
            aiz = fmaf(wiz.z, xv.z, aiz); aiz = fmaf(wiz.w, xv.w, aiz);
            ain = fmaf(win.x, xv.x, ain); ain = fmaf(win.y, xv.y, ain);
            ain = fmaf(win.z, xv.z, ain); ain = fmaf(win.w, xv.w, ain);
            ahr = fmaf(whr.x, hv.x, ahr); ahr = fmaf(whr.y, hv.y, ahr);
            ahr = fmaf(whr.z, hv.z, ahr); ahr = fmaf(whr.w, hv.w, ahr);
            ahz = fmaf(whz.x, hv.x, ahz); ahz = fmaf(whz.y, hv.y, ahz);
            ahz = fmaf(whz.z, hv.z, ahz); ahz = fmaf(whz.w, hv.w, ahz);
            ahn = fmaf(whn.x, hv.x, ahn); ahn = fmaf(whn.y, hv.y, ahn);
            ahn = fmaf(whn.z, hv.z, ahn); ahn = fmaf(whn.w, hv.w, ahn);
        }
        __syncthreads();
    }
    float hp = hin[(size_t)b * H + j];
    float r = sigmoidf_((air + bih[j]) + (ahr + bhh[j]));
    float z = sigmoidf_((aiz + bih[H + j]) + (ahz + bhh[H + j]));
    float n = tanhf((ain + bih[2 * H + j]) + r * (ahn + bhh[2 * H + j]));
    float h = (1.f - z) * n + z * hp;
    hout[(size_t)b * H + j] = h;
    if (cat_aux) cat_aux[(size_t)b * 2 * H + H + j] = h;
}

// Linear: Y[b][jb+c] = X[b] . Wt[jb+c] + bias; grid 256 x 256; 1 whole chain / thread.
__global__ __launch_bounds__(256) void lin_kernel(
    const float* __restrict__ Wt, int wstride, const float* __restrict__ bias,
    const float* __restrict__ X, int xstride, int K, float* __restrict__ Y,
    int reset_keys)
{
    __shared__ float xs[64 * XS_PITCH];
    __shared__ float ws[4 * XS_PITCH];
    const int tid = threadIdx.x;
    const int c = tid & 3, b = tid >> 2;
    const int jb = blockIdx.x * 4;
    if (reset_keys && blockIdx.x == 0 && tid < B) g_keys[tid] = 0ULL;

    float a = 0.f;
    for (int k0 = 0; k0 < K; k0 += 64) {
        for (int i = tid; i < 1024; i += 256) {
            int bb = i >> 4, kg = i & 15;
            *(float4*)(xs + bb * XS_PITCH + kg * 4) =
                *(const float4*)(X + (size_t)bb * xstride + k0 + kg * 4);
        }
        if (tid < 64) {
            int r = tid >> 4, kg = tid & 15;
            *(float4*)(ws + r * XS_PITCH + kg * 4) =
                *(const float4*)(Wt + (size_t)(jb + r) * wstride + k0 + kg * 4);
        }
        __syncthreads();
#pragma unroll
        for (int kk = 0; kk < 64; kk += 4) {
            float4 xv = *(const float4*)(xs + b * XS_PITCH + kk);
            float4 wv = *(const float4*)(ws + c * XS_PITCH + kk);
            a = fmaf(wv.x, xv.x, a); a = fmaf(wv.y, xv.y, a);
            a = fmaf(wv.z, xv.z, a); a = fmaf(wv.w, xv.w, a);
        }
        __syncthreads();
    }
    Y[(size_t)b * H + jb + c] = a + bias[jb + c];
}

// attention: grid 64 blocks x 1024 threads (math identical)
__global__ __launch_bounds__(1024) void attn_kernel(
    const float* __restrict__ q, const float* __restrict__ enc,
    float* __restrict__ cat, float* __restrict__ attn_out, int s)
{
    __shared__ float qs[H];
    __shared__ float wv[TIN];
    __shared__ float red[256];
    const int b = blockIdx.x, tid = threadIdx.x;
    qs[tid] = q[(size_t)b * H + tid];
    __syncthreads();
    const int warp = tid >> 5, lane = tid & 31;
    for (int t = warp; t < TIN; t += 32) {
        const float* e = enc + (size_t)(t * B + b) * H;
        float sacc = 0.f;
#pragma unroll 4
        for (int k = lane; k < H; k += 32) sacc = fmaf(qs[k], e[k], sacc);
        for (int o = 16; o; o >>= 1) sacc += __shfl_xor_sync(0xffffffffu, sacc, o);
        if (!lane) wv[t] = sacc;
    }
    __syncthreads();
    float v = 0.f, ev = 0.f;
    if (tid < 256) { v = wv[tid]; red[tid] = v; }
    __syncthreads();
    for (int st = 128; st; st >>= 1) { if (tid < st) red[tid] = fmaxf(red[tid], red[tid + st]); __syncthreads(); }
    float mx = red[0]; __syncthreads();
    if (tid < 256) { ev = expf(v - mx); red[tid] = ev; }
    __syncthreads();
    for (int st = 128; st; st >>= 1) { if (tid < st) red[tid] += red[tid + st]; __syncthreads(); }
    if (tid < 256) {
        float aw = ev / red[0];
        wv[tid] = aw;
        attn_out[((size_t)b * TIN + tid) * TGT + s] = aw;
    }
    __syncthreads();
    {
        int k = tid;
        float sacc = 0.f;
        for (int t = 0; t < TIN; t++) sacc = fmaf(wv[t], enc[(size_t)(t * B + b) * H + k], sacc);
        cat[(size_t)b * 2 * H + k] = sacc;
    }
}

// fc + fused argmax, register-double-buffered: grid 500 x 256; tile 64m x 64n.
// thread (tx 0..15, ty 0..15) owns m = ty*4+{0..3}, n = n0+tx*4+{0..3}.
// Every output: single-accumulator k-ascending fmaf chain + bias -> bitwise == R6.
#define FCP 68   // smem pitch (floats), multiple of 4 for LDS.128
__global__ __launch_bounds__(256) void fc_argmax(
    const float* __restrict__ A, const float* __restrict__ Wfc,
    const float* __restrict__ bfc, float* __restrict__ out, int s)
{
    __shared__ __align__(16) float As[32 * FCP];   // [k][m]
    __shared__ __align__(16) float Ws[32 * FCP];   // [k][n]
    __shared__ ULL skeys[B];
    const int tid = threadIdx.x;
    const int tx = tid & 15, ty = tid >> 4;
    const int n0 = blockIdx.x * 64;
    if (tid < B) skeys[tid] = 0ULL;

    // prefetch mapping: f4 index i (0..511): row = i>>3 (0..63), kq = i&7 (k = kq*4..kq*4+3)
    const int prow = tid >> 3;            // rows 0..31 (it=0), 32..63 (it=1)
    const int pkq  = tid & 7;
    float4 pa[2], pw[2];
#pragma unroll
    for (int it = 0; it < 2; it++) {
        int row = prow + it * 32;
        pa[it] = *(const float4*)(A   + (size_t)row * H        + pkq * 4);
        pw[it] = *(const float4*)(Wfc + (size_t)(n0 + row) * H + pkq * 4);
    }

    float acc[4][4];
#pragma unroll
    for (int i = 0; i < 4; i++)
#pragma unroll
        for (int jj = 0; jj < 4; jj++) acc[i][jj] = 0.f;

    for (int c = 0; c < 32; c++) {
        __syncthreads();   // previous chunk's smem reads done
#pragma unroll
        for (int it = 0; it < 2; it++) {
            int row = prow + it * 32;
            As[(pkq * 4 + 0) * FCP + row] = pa[it].x;
            As[(pkq * 4 + 1) * FCP + row] = pa[it].y;
            As[(pkq * 4 + 2) * FCP + row] = pa[it].z;
            As[(pkq * 4 + 3) * FCP + row] = pa[it].w;
            Ws[(pkq * 4 + 0) * FCP + row] = pw[it].x;
            Ws[(pkq * 4 + 1) * FCP + row] = pw[it].y;
            Ws[(pkq * 4 + 2) * FCP + row] = pw[it].z;
            Ws[(pkq * 4 + 3) * FCP + row] = pw[it].w;
        }
        __syncthreads();
        if (c < 31) {
            int k0n = (c + 1) * 32;
#pragma unroll
            for (int it = 0; it < 2; it++) {
                int row = prow + it * 32;
                pa[it] = *(const float4*)(A   + (size_t)row * H        + k0n + pkq * 4);
                pw[it] = *(const float4*)(Wfc + (size_t)(n0 + row) * H + k0n + pkq * 4);
            }
        }
#pragma unroll
        for (int k = 0; k < 32; k++) {
            float4 av = *(const float4*)(As + k * FCP + ty * 4);
            float4 wv = *(const float4*)(Ws + k * FCP + tx * 4);
            acc[0][0] = fmaf(av.x, wv.x, acc[0][0]); acc[0][1] = fmaf(av.x, wv.y, acc[0][1]);
            acc[0][2] = fmaf(av.x, wv.z, acc[0][2]); acc[0][3] = fmaf(av.x, wv.w, acc[0][3]);
            acc[1][0] = fmaf(av.y, wv.x, acc[1][0]); acc[1][1] = fmaf(av.y, wv.y, acc[1][1]);
            acc[1][2] = fmaf(av.y, wv.z, acc[1][2]); acc[1][3] = fmaf(av.y, wv.w, acc[1][3]);
            acc[2][0] = fmaf(av.z, wv.x, acc[2][0]); acc[2][1] = fmaf(av.z, wv.y, acc[2][1]);
            acc[2][2] = fmaf(av.z, wv.z, acc[2][2]); acc[2][3] = fmaf(av.z, wv.w, acc[2][3]);
            acc[3][0] = fmaf(av.w, wv.x, acc[3][0]); acc[3][1] = fmaf(av.w, wv.y, acc[3][1]);
            acc[3][2] = fmaf(av.w, wv.z, acc[3][2]); acc[3][3] = fmaf(av.w, wv.w, acc[3][3]);
        }
    }
#pragma unroll
    for (int i = 0; i < 4; i++) {
        int m = ty * 4 + i;
        int nl = n0 + tx * 4;
        float4 vo;
        vo.x = acc[i][0] + bfc[nl];
        vo.y = acc[i][1] + bfc[nl + 1];
        vo.z = acc[i][2] + bfc[nl + 2];
        vo.w = acc[i][3] + bfc[nl + 3];
        *(float4*)(out + ((size_t)m * TGT + s) * V + nl) = vo;
        ULL rowmax = ((ULL)ord32(vo.x) << 15) | (ULL)(V - 1 - nl);
        ULL k1 = ((ULL)ord32(vo.y) << 15) | (ULL)(V - 1 - (nl + 1));
        ULL k2 = ((ULL)ord32(vo.z) << 15) | (ULL)(V - 1 - (nl + 2));
        ULL k3 = ((ULL)ord32(vo.w) << 15) | (ULL)(V - 1 - (nl + 3));
        if (k1 > rowmax) rowmax = k1;
        if (k2 > rowmax) rowmax = k2;
        if (k3 > rowmax) rowmax = k3;
        atomicMax(&skeys[m], rowmax);
    }
    __syncthreads();
    if (tid < B) atomicMax(&g_keys[tid], skeys[tid]);
}

// ================== host orchestration ==================
extern "C" void kernel_launch(void* const* d_in, const int* in_sizes, int n_in,
                              void* d_out_, int out_size) {
    const float* x      = (const float*)d_in[0];
    const float* embed  = (const float*)d_in[1];
    const float* eWih0  = (const float*)d_in[2];
    const float* eWhh0  = (const float*)d_in[3];
    const float* ebih0  = (const float*)d_in[4];
    const float* ebhh0  = (const float*)d_in[5];
    const float* eWih1  = (const float*)d_in[6];
    const float* eWhh1  = (const float*)d_in[7];
    const float* ebih1  = (const float*)d_in[8];
    const float* ebhh1  = (const float*)d_in[9];
    const float* dWih0  = (const float*)d_in[10];
    const float* dWhh0  = (const float*)d_in[11];
    const float* dbih0  = (const float*)d_in[12];
    const float* dbhh0  = (const float*)d_in[13];
    const float* dWih1  = (const float*)d_in[14];
    const float* dWhh1  = (const float*)d_in[15];
    const float* dbih1  = (const float*)d_in[16];
    const float* dbhh1  = (const float*)d_in[17];
    const float* Wq     = (const float*)d_in[18];
    const float* bq     = (const float*)d_in[19];
    const float* Wc     = (const float*)d_in[20];
    const float* bc     = (const float*)d_in[21];
    const float* Wfc    = (const float*)d_in[22];
    const float* bfc    = (const float*)d_in[23];
    float* out = (float*)d_out_;

    const size_t HID_OFF  = (size_t)B * TGT * V;
    const size_t ATTN_OFF = HID_OFF + (size_t)2 * BH;

    float *gi0, *gi1, *h0seq, *enc, *dh0, *dh1, *q, *cat, *comb;
    cudaGetSymbolAddress((void**)&gi0,   g_gi0);
    cudaGetSymbolAddress((void**)&gi1,   g_gi1);
    cudaGetSymbolAddress((void**)&h0seq, g_h0seq);
    cudaGetSymbolAddress((void**)&enc,   g_enc);
    cudaGetSymbolAddress((void**)&dh0,   g_dh0);
    cudaGetSymbolAddress((void**)&dh1,   g_dh1);
    cudaGetSymbolAddress((void**)&q,     g_q);
    cudaGetSymbolAddress((void**)&cat,   g_cat);
    cudaGetSymbolAddress((void**)&comb,  g_comb);

    const int ENC_SMEM = (24 * WS_PITCH + 64 * XS_PITCH) * (int)sizeof(float);
    cudaFuncSetAttribute(enc_recur_kernel, cudaFuncAttributeMaxDynamicSharedMemorySize, ENC_SMEM);

    // ---- encoder ----
    gemm2_tn<<<dim3(H3/128, (B*TIN)/64), 256>>>(x, eWih0, ebih0, gi0, F, F, F, H3);
    enc_recur_kernel<<<128, 256, ENC_SMEM>>>(
        gi0, (long long)H3, (long long)TIN * H3, eWhh0, ebhh0, h0seq);
    gemm2_tn<<<dim3(H3/128, (B*TIN)/64), 256>>>(h0seq, eWih1, ebih1, gi1, H, H, H, H3);
    enc_recur_kernel<<<128, 256, ENC_SMEM>>>(
        gi1, (long long)B * H3, (long long)H3, eWhh1, ebhh1, enc);

    // ---- decoder: 6 kernels per step ----
    for (int s = 0; s < TGT; s++) {
        const float* h0in = s ? (dh0 + (size_t)((s - 1) & 1) * BH) : (h0seq + (size_t)(TIN - 1) * BH);
        const float* h1in = s ? (dh1 + (size_t)((s - 1) & 1) * BH) : (enc + (size_t)(TIN - 1) * BH);
        float* h0out = dh0 + (size_t)(s & 1) * BH;
        float* h1out = dh1 + (size_t)(s & 1) * BH;

        dec_gru<<<256, 256>>>(embed, H, 1, s, dWih0, dbih0, h0in, dWhh0, dbhh0, h0out, nullptr);
        dec_gru<<<256, 256>>>(h0out, H, 0, s, dWih1, dbih1, h1in, dWhh1, dbhh1, h1out, cat);
        lin_kernel<<<256, 256>>>(Wq, H, bq, h1out, H, H, q, 0);
        attn_kernel<<<B, 1024>>>(q, enc, cat, out + ATTN_OFF, s);
        lin_kernel<<<256, 256>>>(Wc, 2 * H, bc, cat, 2 * H, 2 * H, comb, 1);  // also resets g_keys
        fc_argmax<<<V / 64, 256>>>(comb, Wfc, bfc, out, s);
    }

    // ---- final hidden [2,B,H]: decoder (h0,h1) after step TGT-1 (parity 1) ----
    cudaMemcpyAsync(out + HID_OFF,      dh0 + BH, (size_t)BH * sizeof(float), cudaMemcpyDeviceToDevice);
    cudaMemcpyAsync(out + HID_OFF + BH, dh1 + BH, (size_t)BH * sizeof(float), cudaMemcpyDeviceToDevice);
}

// round 12
// speedup vs baseline: 1.1844x; 1.0643x over previous
#include <cuda_runtime.h>
#include <cuda_bf16.h>
#include <cfloat>
#include <cstddef>
#include <cstdint>

#define B 64
#define TIN 256
#define F 64
#define H 1024
#define H3 3072
#define TGT 64
#define V 32000
#define BH (B*H)
typedef unsigned long long ULL;
typedef unsigned int uint;

__device__ float g_gi0[(size_t)TIN * B * H3];   // reused for Wfc bf16 hi/mid/lo after encoder
__device__ float g_gi1[(size_t)TIN * B * H3];
__device__ float g_h0seq[(size_t)TIN * BH];
__device__ float g_enc[(size_t)TIN * BH];
__device__ float g_dh0[2 * BH];
__device__ float g_dh1[2 * BH];
__device__ float g_q[BH];
__device__ float g_cat[B * 2 * H];
__device__ float g_comb[BH];
__device__ __nv_bfloat16 g_ch[BH], g_cm[BH], g_cl[BH];
__device__ ULL g_keys[B];
__device__ unsigned long long g_bar64;

__device__ __forceinline__ void grid_sync() {
    __syncthreads();
    if (threadIdx.x == 0) {
        __threadfence();
        unsigned long long old = atomicAdd(&g_bar64, 1ULL);
        unsigned gen = (unsigned)(old >> 32);
        if ((unsigned)old == gridDim.x - 1)
            atomicAdd(&g_bar64, (1ULL << 32) - (unsigned long long)gridDim.x);
        else
            while ((unsigned)((*(volatile unsigned long long*)&g_bar64) >> 32) == gen) { }
        __threadfence();
    }
    __syncthreads();
}
__device__ __forceinline__ float sigmoidf_(float x) { return 1.f / (1.f + expf(-x)); }
__device__ __forceinline__ void fma2(ULL& d, ULL a, ULL b) {
    asm("fma.rn.f32x2 %0, %1, %2, %0;" : "+l"(d) : "l"(a), "l"(b));
}
__device__ __forceinline__ float2 unpack2(ULL v) {
    float2 r; asm("mov.b64 {%0, %1}, %2;" : "=f"(r.x), "=f"(r.y) : "l"(v)); return r;
}
__device__ __forceinline__ uint ord32(float f) {
    uint u = __float_as_uint(f);
    return u ^ ((u >> 31) ? 0xFFFFFFFFu : 0x80000000u);
}
__device__ __forceinline__ uint32_t smem_u32(const void* p) {
    uint32_t a;
    asm("{ .reg .u64 t; cvta.to.shared.u64 t, %1; cvt.u32.u64 %0, t; }" : "=r"(a) : "l"(p));
    return a;
}
// ---- legacy tensor-core path (supported on sm_103 non-'a') ----
__device__ __forceinline__ void ldmA(uint32_t* a, uint32_t addr) {
    asm volatile("ldmatrix.sync.aligned.m8n8.x4.shared.b16 {%0,%1,%2,%3}, [%4];"
                 : "=r"(a[0]), "=r"(a[1]), "=r"(a[2]), "=r"(a[3]) : "r"(addr));
}
__device__ __forceinline__ void ldmB(uint32_t* b, uint32_t addr) {
    asm volatile("ldmatrix.sync.aligned.m8n8.x2.shared.b16 {%0,%1}, [%2];"
                 : "=r"(b[0]), "=r"(b[1]) : "r"(addr));
}
__device__ __forceinline__ void mma16816(float* d, const uint32_t* a, const uint32_t* b) {
    asm volatile("mma.sync.aligned.m16n8k16.row.col.f32.bf16.bf16.f32 "
                 "{%0,%1,%2,%3},{%4,%5,%6,%7},{%8,%9},{%0,%1,%2,%3};"
                 : "+f"(d[0]), "+f"(d[1]), "+f"(d[2]), "+f"(d[3])
                 : "r"(a[0]), "r"(a[1]), "r"(a[2]), "r"(a[3]), "r"(b[0]), "r"(b[1]));
}

// ===== FMA2 GEMM (proven): C = A @ W^T + bias, tile 64x128 =====
__global__ __launch_bounds__(256) void gemm2_tn(
    const float* __restrict__ A, const float* __restrict__ W,
    const float* __restrict__ bias, float* __restrict__ C, int K, int lda, int ldw, int ldc)
{
    __shared__ __align__(16) ULL smu2[2 * 64 * 33];
    ULL* As2 = smu2; ULL* Ws2 = smu2 + 64 * 33;
    const int tid = threadIdx.x, tx = tid & 15, ty = tid >> 4;
    const int m0 = blockIdx.y * 64, n0 = blockIdx.x * 128;
    ULL acc[4][4];
#pragma unroll
    for (int r = 0; r < 4; r++)
#pragma unroll
        for (int q = 0; q < 4; q++) acc[r][q] = 0ULL;
    for (int k0 = 0; k0 < K; k0 += 32) {
        for (int i = tid; i < 2048; i += 256) {
            int m = i >> 5, k = i & 31;
            float v = A[(size_t)(m0 + m) * lda + k0 + k];
            ((float2*)As2)[m * 33 + k] = make_float2(v, v);
        }
        for (int i = tid; i < 2048; i += 256) {
            int pc = i >> 5, k = i & 31;
            int n_lo = n0 + (pc >> 4) * 32 + (pc & 15);
            ((float2*)Ws2)[pc * 33 + k] = make_float2(W[(size_t)n_lo * ldw + k0 + k], W[(size_t)(n_lo + 16) * ldw + k0 + k]);
        }
        __syncthreads();
#pragma unroll 8
        for (int k = 0; k < 32; k++) {
            ULL a0 = As2[ty*33+k], a1 = As2[(ty+16)*33+k], a2 = As2[(ty+32)*33+k], a3 = As2[(ty+48)*33+k];
            ULL w0 = Ws2[tx*33+k], w1 = Ws2[(16+tx)*33+k], w2 = Ws2[(32+tx)*33+k], w3 = Ws2[(48+tx)*33+k];
            fma2(acc[0][0],w0,a0); fma2(acc[0][1],w1,a0); fma2(acc[0][2],w2,a0); fma2(acc[0][3],w3,a0);
            fma2(acc[1][0],w0,a1); fma2(acc[1][1],w1,a1); fma2(acc[1][2],w2,a1); fma2(acc[1][3],w3,a1);
            fma2(acc[2][0],w0,a2); fma2(acc[2][1],w1,a2); fma2(acc[2][2],w2,a2); fma2(acc[2][3],w3,a2);
            fma2(acc[3][0],w0,a3); fma2(acc[3][1],w1,a3); fma2(acc[3][2],w2,a3); fma2(acc[3][3],w3,a3);
        }
        __syncthreads();
    }
#pragma unroll
    for (int r = 0; r < 4; r++) {
        int m = m0 + ty + 16 * r;
#pragma unroll
        for (int q = 0; q < 4; q++) {
            float2 v = unpack2(acc[r][q]);
            int n_lo = n0 + q * 32 + tx;
            C[(size_t)m * ldc + n_lo] = v.x + bias[n_lo];
            C[(size_t)m * ldc + n_lo + 16] = v.y + bias[n_lo + 16];
        }
    }
}

// ===== persistent encoder recurrence (proven, unchanged) =====
#define WS_PITCH 1028
#define XS_PITCH 68
__global__ __launch_bounds__(256, 1) void enc_recur_kernel(
    const float* __restrict__ gi, long long gi_t_stride, long long gi_b_stride,
    const float* __restrict__ Whh, const float* __restrict__ bhh, float* __restrict__ hseq)
{
    extern __shared__ float sm[];
    float* ws = sm; float* xs = sm + 24 * WS_PITCH;
    const int tid = threadIdx.x, c = tid & 7, bq = tid >> 3;
    const int jb = blockIdx.x * 8, b0 = 2 * bq, b1 = b0 + 1, j = jb + c;
    for (int i = tid; i < 24 * 256; i += 256) {
        int r = i >> 8, kg = i & 255;
        int wr = (r >> 3) * H + jb + (r & 7);
        *(float4*)(ws + r * WS_PITCH + kg * 4) = *(const float4*)(Whh + (size_t)wr * H + kg * 4);
    }
    const float br = bhh[j], bz = bhh[H + j], bn = bhh[2 * H + j];
    __syncthreads();
    for (int t = 0; t < TIN; t++) {
        float ar0=0.f,ar1=0.f,az0=0.f,az1=0.f,an0=0.f,an1=0.f;
        const float* hprev = hseq + (size_t)(t - 1) * BH;
        if (t > 0) {
            for (int k0 = 0; k0 < H; k0 += 64) {
                for (int i = tid; i < 1024; i += 256) {
                    int b = i >> 4, kg = i & 15;
                    *(float4*)(xs + b * XS_PITCH + kg * 4) = *(const float4*)(hprev + (size_t)b * H + k0 + kg * 4);
                }
                __syncthreads();
#pragma unroll
                for (int kk = 0; kk < 64; kk += 4) {
                    float4 x0 = *(const float4*)(xs + b0 * XS_PITCH + kk);
                    float4 x1 = *(const float4*)(xs + b1 * XS_PITCH + kk);
                    float4 w0 = *(const float4*)(ws + c * WS_PITCH + k0 + kk);
                    float4 w1 = *(const float4*)(ws + (8 + c) * WS_PITCH + k0 + kk);
                    float4 w2 = *(const float4*)(ws + (16 + c) * WS_PITCH + k0 + kk);
                    ar0=fmaf(w0.x,x0.x,ar0); ar0=fmaf(w0.y,x0.y,ar0); ar0=fmaf(w0.z,x0.z,ar0); ar0=fmaf(w0.w,x0.w,ar0);
                    ar1=fmaf(w0.x,x1.x,ar1); ar1=fmaf(w0.y,x1.y,ar1); ar1=fmaf(w0.z,x1.z,ar1); ar1=fmaf(w0.w,x1.w,ar1);
                    az0=fmaf(w1.x,x0.x,az0); az0=fmaf(w1.y,x0.y,az0); az0=fmaf(w1.z,x0.z,az0); az0=fmaf(w1.w,x0.w,az0);
                    az1=fmaf(w1.x,x1.x,az1); az1=fmaf(w1.y,x1.y,az1); az1=fmaf(w1.z,x1.z,az1); az1=fmaf(w1.w,x1.w,az1);
                    an0=fmaf(w2.x,x0.x,an0); an0=fmaf(w2.y,x0.y,an0); an0=fmaf(w2.z,x0.z,an0); an0=fmaf(w2.w,x0.w,an0);
                    an1=fmaf(w2.x,x1.x,an1); an1=fmaf(w2.y,x1.y,an1); an1=fmaf(w2.z,x1.z,an1); an1=fmaf(w2.w,x1.w,an1);
                }
                __syncthreads();
            }
        }
        const float* gr0 = gi + (size_t)b0 * gi_b_stride + (size_t)t * gi_t_stride;
        const float* gr1 = gi + (size_t)b1 * gi_b_stride + (size_t)t * gi_t_stride;
        float* hout = hseq + (size_t)t * BH;
        float hp0 = (t > 0) ? hprev[(size_t)b0 * H + j] : 0.f;
        float hp1 = (t > 0) ? hprev[(size_t)b1 * H + j] : 0.f;
        {
            float r = sigmoidf_(gr0[j] + ar0 + br);
            float z = sigmoidf_(gr0[H + j] + az0 + bz);
            float n = tanhf(gr0[2 * H + j] + r * (an0 + bn));
            hout[(size_t)b0 * H + j] = (1.f - z) * n + z * hp0;
        }
        {
            float r = sigmoidf_(gr1[j] + ar1 + br);
            float z = sigmoidf_(gr1[H + j] + az1 + bz);
            float n = tanhf(gr1[2 * H + j] + r * (an1 + bn));
            hout[(size_t)b1 * H + j] = (1.f - z) * n + z * hp1;
        }
        grid_sync();
    }
}

// ===== Wfc 3-way bf16 split (one-time) =====
__global__ __launch_bounds__(256) void split_w_kernel(
    const float* __restrict__ W, __nv_bfloat16* __restrict__ Wh,
    __nv_bfloat16* __restrict__ Wm, __nv_bfloat16* __restrict__ Wl, size_t n)
{
    for (size_t i = (size_t)blockIdx.x * 256 + threadIdx.x; i < n; i += (size_t)gridDim.x * 256) {
        float v = W[i];
        __nv_bfloat16 h = __float2bfloat16(v); float r1 = v - __bfloat162float(h);
        __nv_bfloat16 m = __float2bfloat16(r1);
        Wh[i] = h; Wm[i] = m; Wl[i] = __float2bfloat16(r1 - __bfloat162float(m));
    }
}

// ===== decoder GRU (proven, unchanged) =====
__global__ __launch_bounds__(256) void dec_gru(
    const float* __restrict__ x, int xstride, int use_tok, int s,
    const float* __restrict__ Wih, const float* __restrict__ bih, const float* __restrict__ hin,
    const float* __restrict__ Whh, const float* __restrict__ bhh,
    float* __restrict__ hout, float* __restrict__ cat_aux)
{
    __shared__ float xs[64 * XS_PITCH], hs[64 * XS_PITCH], wi[12 * XS_PITCH], wh[12 * XS_PITCH];
    __shared__ int toks[B];
    const int tid = threadIdx.x, c = tid & 3, b = tid >> 2;
    const int jb = blockIdx.x * 4, j = jb + c;
    if (use_tok && tid < B) toks[tid] = (s == 0) ? 0 : (V - 1 - (int)(g_keys[tid] & 0x7FFFULL));
    __syncthreads();
    float air=0.f,aiz=0.f,ain=0.f,ahr=0.f,ahz=0.f,ahn=0.f;
    for (int k0 = 0; k0 < H; k0 += 64) {
        for (int i = tid; i < 1024; i += 256) {
            int bb = i >> 4, kg = i & 15;
            const float* xr = use_tok ? (x + (size_t)toks[bb] * xstride) : (x + (size_t)bb * xstride);
            *(float4*)(xs + bb * XS_PITCH + kg * 4) = *(const float4*)(xr + k0 + kg * 4);
            *(float4*)(hs + bb * XS_PITCH + kg * 4) = *(const float4*)(hin + (size_t)bb * H + k0 + kg * 4);
        }
        if (tid < 192) {
            int r = tid >> 4, kg = tid & 15;
            int wr = (r >> 2) * H + jb + (r & 3);
            *(float4*)(wi + r * XS_PITCH + kg * 4) = *(const float4*)(Wih + (size_t)wr * H + k0 + kg * 4);
            *(float4*)(wh + r * XS_PITCH + kg * 4) = *(const float4*)(Whh + (size_t)wr * H + k0 + kg * 4);
        }
        __syncthreads();
#pragma unroll
        for (int kk = 0; kk < 64; kk += 4) {
            float4 xv = *(const float4*)(xs + b * XS_PITCH + kk);
            float4 hv = *(const float4*)(hs + b * XS_PITCH + kk);
            float4 wir = *(const float4*)(wi + c * XS_PITCH + kk);
            float4 wiz = *(const float4*)(wi + (4 + c) * XS_PITCH + kk);
            float4 win = *(const float4*)(wi + (8 + c) * XS_PITCH + kk);
            float4 whr = *(const float4*)(wh + c * XS_PITCH + kk);
            float4 whz = *(const float4*)(wh + (4 + c) * XS_PITCH + kk);
            float4 whn = *(const float4*)(wh + (8 + c) * XS_PITCH + kk);
            air=fmaf(wir.x,xv.x,air); air=fmaf(wir.y,xv.y,air); air=fmaf(wir.z,xv.z,air); air=fmaf(wir.w,xv.w,air);
            aiz=fmaf(wiz.x,xv.x,aiz); aiz=fmaf(wiz.y,xv.y,aiz); aiz=fmaf(wiz.z,xv.z,aiz); aiz=fmaf(wiz.w,xv.w,aiz);
            ain=fmaf(win.x,xv.x,ain); ain=fmaf(win.y,xv.y,ain); ain=fmaf(win.z,xv.z,ain); ain=fmaf(win.w,xv.w,ain);
            ahr=fmaf(whr.x,hv.x,ahr); ahr=fmaf(whr.y,hv.y,ahr); ahr=fmaf(whr.z,hv.z,ahr); ahr=fmaf(whr.w,hv.w,ahr);
            ahz=fmaf(whz.x,hv.x,ahz); ahz=fmaf(whz.y,hv.y,ahz); ahz=fmaf(whz.z,hv.z,ahz); ahz=fmaf(whz.w,hv.w,ahz);
            ahn=fmaf(whn.x,hv.x,ahn); ahn=fmaf(whn.y,hv.y,ahn); ahn=fmaf(whn.z,hv.z,ahn); ahn=fmaf(whn.w,hv.w,ahn);
        }
        __syncthreads();
    }
    float hp = hin[(size_t)b * H + j];
    float r = sigmoidf_((air + bih[j]) + (ahr + bhh[j]));
    float z = sigmoidf_((aiz + bih[H + j]) + (ahz + bhh[H + j]));
    float n = tanhf((ain + bih[2 * H + j]) + r * (ahn + bhh[2 * H + j]));
    float h = (1.f - z) * n + z * hp;
    hout[(size_t)b * H + j] = h;
    if (cat_aux) cat_aux[(size_t)b * 2 * H + H + j] = h;
}

// ===== linear (optional 3-way bf16 split of result) =====
__global__ __launch_bounds__(256) void lin_kernel(
    const float* __restrict__ Wt, int wstride, const float* __restrict__ bias,
    const float* __restrict__ X, int xstride, int K, float* __restrict__ Y,
    int reset_keys, int write_split)
{
    __shared__ float xs[64 * XS_PITCH], ws[4 * XS_PITCH];
    const int tid = threadIdx.x, c = tid & 3, b = tid >> 2;
    const int jb = blockIdx.x * 4;
    if (reset_keys && blockIdx.x == 0 && tid < B) g_keys[tid] = 0ULL;
    float a = 0.f;
    for (int k0 = 0; k0 < K; k0 += 64) {
        for (int i = tid; i < 1024; i += 256) {
            int bb = i >> 4, kg = i & 15;
            *(float4*)(xs + bb * XS_PITCH + kg * 4) = *(const float4*)(X + (size_t)bb * xstride + k0 + kg * 4);
        }
        if (tid < 64) {
            int r = tid >> 4, kg = tid & 15;
            *(float4*)(ws + r * XS_PITCH + kg * 4) = *(const float4*)(Wt + (size_t)(jb + r) * wstride + k0 + kg * 4);
        }
        __syncthreads();
#pragma unroll
        for (int kk = 0; kk < 64; kk += 4) {
            float4 xv = *(const float4*)(xs + b * XS_PITCH + kk);
            float4 wv = *(const float4*)(ws + c * XS_PITCH + kk);
            a = fmaf(wv.x, xv.x, a); a = fmaf(wv.y, xv.y, a);
            a = fmaf(wv.z, xv.z, a); a = fmaf(wv.w, xv.w, a);
        }
        __syncthreads();
    }
    float v = a + bias[jb + c];
    size_t idx = (size_t)b * H + jb + c;
    Y[idx] = v;
    if (write_split) {
        __nv_bfloat16 hv = __float2bfloat16(v); float r1 = v - __bfloat162float(hv);
        __nv_bfloat16 mv = __float2bfloat16(r1);
        g_ch[idx] = hv; g_cm[idx] = mv; g_cl[idx] = __float2bfloat16(r1 - __bfloat162float(mv));
    }
}

// ===== attention (unchanged) =====
__global__ __launch_bounds__(1024) void attn_kernel(
    const float* __restrict__ q, const float* __restrict__ enc,
    float* __restrict__ cat, float* __restrict__ attn_out, int s)
{
    __shared__ float qs[H], wv[TIN], red[256];
    const int b = blockIdx.x, tid = threadIdx.x;
    qs[tid] = q[(size_t)b * H + tid];
    __syncthreads();
    const int warp = tid >> 5, lane = tid & 31;
    for (int t = warp; t < TIN; t += 32) {
        const float* e = enc + (size_t)(t * B + b) * H;
        float sacc = 0.f;
#pragma unroll 4
        for (int k = lane; k < H; k += 32) sacc = fmaf(qs[k], e[k], sacc);
        for (int o = 16; o; o >>= 1) sacc += __shfl_xor_sync(0xffffffffu, sacc, o);
        if (!lane) wv[t] = sacc;
    }
    __syncthreads();
    float v = 0.f, ev = 0.f;
    if (tid < 256) { v = wv[tid]; red[tid] = v; }
    __syncthreads();
    for (int st = 128; st; st >>= 1) { if (tid < st) red[tid] = fmaxf(red[tid], red[tid + st]); __syncthreads(); }
    float mx = red[0]; __syncthreads();
    if (tid < 256) { ev = expf(v - mx); red[tid] = ev; }
    __syncthreads();
    for (int st = 128; st; st >>= 1) { if (tid < st) red[tid] += red[tid + st]; __syncthreads(); }
    if (tid < 256) {
        float aw = ev / red[0];
        wv[tid] = aw;
        attn_out[((size_t)b * TIN + tid) * TGT + s] = aw;
    }
    __syncthreads();
    {
        int k = tid; float sacc = 0.f;
        for (int t = 0; t < TIN; t++) sacc = fmaf(wv[t], enc[(size_t)(t * B + b) * H + k], sacc);
        cat[(size_t)b * 2 * H + k] = sacc;
    }
}

// ===== fc on mma.sync (HMMA): 6-term 3-way bf16 split, fp32 acc; fused argmax =====
// grid 250 x 256 (8 warps: 2m x 4n). Block tile M=64, N=128. K chunks of 32, all splits per chunk.
#define AP 40
__global__ __launch_bounds__(256) void fc_mma(
    const __nv_bfloat16* __restrict__ Wh, const __nv_bfloat16* __restrict__ Wm,
    const __nv_bfloat16* __restrict__ Wl, const float* __restrict__ bfc,
    float* __restrict__ out, int s)
{
    __shared__ __align__(16) __nv_bfloat16 Asm[3][64][AP];
    __shared__ __align__(16) __nv_bfloat16 Wsm[3][128][AP];
    __shared__ ULL skeys[B];
    const int tid = threadIdx.x, lane = tid & 31, warp = tid >> 5;
    const int wm = warp >> 2, wn = warp & 3;
    const int n0 = blockIdx.x * 128;
    if (tid < B) skeys[tid] = 0ULL;

    const __nv_bfloat16* Asrc[3] = { g_ch, g_cm, g_cl };
    const __nv_bfloat16* Wsrc[3] = { Wh, Wm, Wl };

    const int arow = tid >> 2, aq = tid & 3;   // A: 64 rows x 4 uint4 (32 bf16)
    uint4 pa[3], pw[3][2];
#pragma unroll
    for (int sp = 0; sp < 3; sp++) {
        pa[sp] = *(const uint4*)(Asrc[sp] + (size_t)arow * H + aq * 8);
#pragma unroll
        for (int t = 0; t < 2; t++) {
            int i = tid + t * 256, row = i >> 2, q = i & 3;
            pw[sp][t] = *(const uint4*)(Wsrc[sp] + (size_t)(n0 + row) * H + q * 8);
        }
    }

    float acc[2][4][4];
#pragma unroll
    for (int mt = 0; mt < 2; mt++)
#pragma unroll
        for (int nt = 0; nt < 4; nt++)
#pragma unroll
            for (int r = 0; r < 4; r++) acc[mt][nt][r] = 0.f;

    for (int c = 0; c < 32; c++) {
        __syncthreads();
#pragma unroll
        for (int sp = 0; sp < 3; sp++) {
            *(uint4*)(&Asm[sp][arow][aq * 8]) = pa[sp];
#pragma unroll
            for (int t = 0; t < 2; t++) {
                int i = tid + t * 256, row = i >> 2, q = i & 3;
                *(uint4*)(&Wsm[sp][row][q * 8]) = pw[sp][t];
            }
        }
        __syncthreads();
        if (c < 31) {
            int k0 = (c + 1) * 32;
#pragma unroll
            for (int sp = 0; sp < 3; sp++) {
                pa[sp] = *(const uint4*)(Asrc[sp] + (size_t)arow * H + k0 + aq * 8);
#pragma unroll
                for (int t = 0; t < 2; t++) {
                    int i = tid + t * 256, row = i >> 2, q = i & 3;
                    pw[sp][t] = *(const uint4*)(Wsrc[sp] + (size_t)(n0 + row) * H + k0 + q * 8);
                }
            }
        }
#pragma unroll
        for (int k16 = 0; k16 < 2; k16++) {
            uint32_t af[3][2][4];
#pragma unroll
            for (int sp = 0; sp < 3; sp++)
#pragma unroll
                for (int mt = 0; mt < 2; mt++)
                    ldmA(af[sp][mt], smem_u32(&Asm[sp][wm * 32 + mt * 16 + (lane & 15)][k16 * 16 + (lane >> 4) * 8]));
#pragma unroll
            for (int nt = 0; nt < 4; nt++) {
                uint32_t bfr[3][2];
#pragma unroll
                for (int sp = 0; sp < 3; sp++)
                    ldmB(bfr[sp], smem_u32(&Wsm[sp][wn * 32 + nt * 8 + (lane & 7)][k16 * 16 + ((lane >> 3) & 1) * 8]));
#pragma unroll
                for (int mt = 0; mt < 2; mt++) {
                    mma16816(acc[mt][nt], af[0][mt], bfr[0]);   // ah*wh
                    mma16816(acc[mt][nt], af[0][mt], bfr[1]);   // ah*wm
                    mma16816(acc[mt][nt], af[1][mt], bfr[0]);   // am*wh
                    mma16816(acc[mt][nt], af[0][mt], bfr[2]);   // ah*wl
                    mma16816(acc[mt][nt], af[1][mt], bfr[1]);   // am*wm
                    mma16816(acc[mt][nt], af[2][mt], bfr[0]);   // al*wh
                }
            }
        }
    }
    // epilogue: bias + store + argmax keys
#pragma unroll
    for (int mt = 0; mt < 2; mt++)
#pragma unroll
        for (int half = 0; half < 2; half++) {
            int m = wm * 32 + mt * 16 + half * 8 + (lane >> 2);
            float* orow = out + ((size_t)m * TGT + s) * V;
            ULL rmax = 0ULL;
#pragma unroll
            for (int nt = 0; nt < 4; nt++) {
                int n = n0 + wn * 32 + nt * 8 + (lane & 3) * 2;
                float v0 = acc[mt][nt][half * 2 + 0] + bfc[n];
                float v1 = acc[mt][nt][half * 2 + 1] + bfc[n + 1];
                *(float2*)(orow + n) = make_float2(v0, v1);
                ULL k0b = ((ULL)ord32(v0) << 15) | (ULL)(V - 1 - n);
                ULL k1b = ((ULL)ord32(v1) << 15) | (ULL)(V - 2 - n);
                if (k0b > rmax) rmax = k0b;
                if (k1b > rmax) rmax = k1b;
            }
            atomicMax(&skeys[m], rmax);
        }
    __syncthreads();
    if (tid < B) atomicMax(&g_keys[tid], skeys[tid]);
}

// ===== host =====
extern "C" void kernel_launch(void* const* d_in, const int* in_sizes, int n_in,
                              void* d_out_, int out_size) {
    const float* x = (const float*)d_in[0];
    const float* embed = (const float*)d_in[1];
    const float* eWih0 = (const float*)d_in[2];  const float* eWhh0 = (const float*)d_in[3];
    const float* ebih0 = (const float*)d_in[4];  const float* ebhh0 = (const float*)d_in[5];
    const float* eWih1 = (const float*)d_in[6];  const float* eWhh1 = (const float*)d_in[7];
    const float* ebih1 = (const float*)d_in[8];  const float* ebhh1 = (const float*)d_in[9];
    const float* dWih0 = (const float*)d_in[10]; const float* dWhh0 = (const float*)d_in[11];
    const float* dbih0 = (const float*)d_in[12]; const float* dbhh0 = (const float*)d_in[13];
    const float* dWih1 = (const float*)d_in[14]; const float* dWhh1 = (const float*)d_in[15];
    const float* dbih1 = (const float*)d_in[16]; const float* dbhh1 = (const float*)d_in[17];
    const float* Wq = (const float*)d_in[18];    const float* bq = (const float*)d_in[19];
    const float* Wc = (const float*)d_in[20];    const float* bc = (const float*)d_in[21];
    const float* Wfc = (const float*)d_in[22];   const float* bfc = (const float*)d_in[23];
    float* out = (float*)d_out_;
    const size_t HID_OFF = (size_t)B * TGT * V;
    const size_t ATTN_OFF = HID_OFF + (size_t)2 * BH;

    float *gi0, *gi1, *h0seq, *enc, *dh0, *dh1, *q, *cat, *comb;
    cudaGetSymbolAddress((void**)&gi0, g_gi0);
    cudaGetSymbolAddress((void**)&gi1, g_gi1);
    cudaGetSymbolAddress((void**)&h0seq, g_h0seq);
    cudaGetSymbolAddress((void**)&enc, g_enc);
    cudaGetSymbolAddress((void**)&dh0, g_dh0);
    cudaGetSymbolAddress((void**)&dh1, g_dh1);
    cudaGetSymbolAddress((void**)&q, g_q);
    cudaGetSymbolAddress((void**)&cat, g_cat);
    cudaGetSymbolAddress((void**)&comb, g_comb);
    __nv_bfloat16* Wh = (__nv_bfloat16*)gi0;
    __nv_bfloat16* Wm = Wh + (size_t)V * H;
    __nv_bfloat16* Wl = Wm + (size_t)V * H;

    const int ENC_SMEM = (24 * WS_PITCH + 64 * XS_PITCH) * (int)sizeof(float);
    cudaFuncSetAttribute(enc_recur_kernel, cudaFuncAttributeMaxDynamicSharedMemorySize, ENC_SMEM);

    gemm2_tn<<<dim3(H3/128, (B*TIN)/64), 256>>>(x, eWih0, ebih0, gi0, F, F, F, H3);
    enc_recur_kernel<<<128, 256, ENC_SMEM>>>(gi0, (long long)H3, (long long)TIN * H3, eWhh0, ebhh0, h0seq);
    gemm2_tn<<<dim3(H3/128, (B*TIN)/64), 256>>>(h0seq, eWih1, ebih1, gi1, H, H, H, H3);
    enc_recur_kernel<<<128, 256, ENC_SMEM>>>(gi1, (long long)B * H3, (long long)H3, eWhh1, ebhh1, enc);
    split_w_kernel<<<1024, 256>>>(Wfc, Wh, Wm, Wl, (size_t)V * H);   // gi0 free after enc layer 0

    for (int s = 0; s < TGT; s++) {
        const float* h0in = s ? (dh0 + (size_t)((s - 1) & 1) * BH) : (h0seq + (size_t)(TIN - 1) * BH);
        const float* h1in = s ? (dh1 + (size_t)((s - 1) & 1) * BH) : (enc + (size_t)(TIN - 1) * BH);
        float* h0out = dh0 + (size_t)(s & 1) * BH;
        float* h1out = dh1 + (size_t)(s & 1) * BH;
        dec_gru<<<256, 256>>>(embed, H, 1, s, dWih0, dbih0, h0in, dWhh0, dbhh0, h0out, nullptr);
        dec_gru<<<256, 256>>>(h0out, H, 0, s, dWih1, dbih1, h1in, dWhh1, dbhh1, h1out, cat);
        lin_kernel<<<256, 256>>>(Wq, H, bq, h1out, H, H, q, 0, 0);
        attn_kernel<<<B, 1024>>>(q, enc, cat, out + ATTN_OFF, s);
        lin_kernel<<<256, 256>>>(Wc, 2 * H, bc, cat, 2 * H, 2 * H, comb, 1, 1);
        fc_mma<<<V / 128, 256>>>(Wh, Wm, Wl, bfc, out, s);
    }
    cudaMemcpyAsync(out + HID_OFF,      dh0 + BH, (size_t)BH * sizeof(float), cudaMemcpyDeviceToDevice);
    cudaMemcpyAsync(out + HID_OFF + BH, dh1 + BH, (size_t)BH * sizeof(float), cudaMemcpyDeviceToDevice);
}

// round 14
// speedup vs baseline: 1.3676x; 1.1547x over previous
#include <cuda_runtime.h>
#include <cuda_bf16.h>
#include <cfloat>
#include <cstddef>
#include <cstdint>

#define B 64
#define TIN 256
#define F 64
#define H 1024
#define H3 3072
#define TGT 64
#define V 32000
#define BH (B*H)
typedef unsigned long long ULL;
typedef unsigned int uint;
typedef __nv_bfloat16 bf16;

__device__ float g_gi0[(size_t)TIN * B * H3];   // reused: Wfc bf16 splits
__device__ float g_gi1[(size_t)TIN * B * H3];   // reused: GRU weight bf16 splits
__device__ float g_h0seq[(size_t)TIN * BH];
__device__ float g_enc[(size_t)TIN * BH];
__device__ float g_dh0[2 * BH];
__device__ float g_dh1[2 * BH];
__device__ float g_q[BH];
__device__ float g_cat[B * 2 * H];
__device__ float g_comb[BH];
__device__ float g_Ygi[(size_t)B * H3];
__device__ float g_Ygh[(size_t)B * H3];
__device__ bf16 g_ch[BH], g_cm[BH], g_cl[BH];
__device__ bf16 g_xe[3 * BH];
__device__ bf16 g_h0s[2 * 3 * BH];
__device__ bf16 g_h1s[2 * 3 * BH];
__device__ ULL g_keys[B];
__device__ unsigned long long g_bar64;

__device__ __forceinline__ void grid_sync() {
    __syncthreads();
    if (threadIdx.x == 0) {
        __threadfence();
        unsigned long long old = atomicAdd(&g_bar64, 1ULL);
        unsigned gen = (unsigned)(old >> 32);
        if ((unsigned)old == gridDim.x - 1)
            atomicAdd(&g_bar64, (1ULL << 32) - (unsigned long long)gridDim.x);
        else
            while ((unsigned)((*(volatile unsigned long long*)&g_bar64) >> 32) == gen) { }
        __threadfence();
    }
    __syncthreads();
}
__device__ __forceinline__ float sigmoidf_(float x) { return 1.f / (1.f + expf(-x)); }
__device__ __forceinline__ void fma2(ULL& d, ULL a, ULL b) {
    asm("fma.rn.f32x2 %0, %1, %2, %0;" : "+l"(d) : "l"(a), "l"(b));
}
__device__ __forceinline__ float2 unpack2(ULL v) {
    float2 r; asm("mov.b64 {%0, %1}, %2;" : "=f"(r.x), "=f"(r.y) : "l"(v)); return r;
}
__device__ __forceinline__ uint ord32(float f) {
    uint u = __float_as_uint(f);
    return u ^ ((u >> 31) ? 0xFFFFFFFFu : 0x80000000u);
}
__device__ __forceinline__ uint32_t smem_u32(const void* p) {
    uint32_t a;
    asm("{ .reg .u64 t; cvta.to.shared.u64 t, %1; cvt.u32.u64 %0, t; }" : "=r"(a) : "l"(p));
    return a;
}
__device__ __forceinline__ void ldmA(uint32_t* a, uint32_t addr) {
    asm volatile("ldmatrix.sync.aligned.m8n8.x4.shared.b16 {%0,%1,%2,%3}, [%4];"
                 : "=r"(a[0]), "=r"(a[1]), "=r"(a[2]), "=r"(a[3]) : "r"(addr));
}
__device__ __forceinline__ void ldmB(uint32_t* b, uint32_t addr) {
    asm volatile("ldmatrix.sync.aligned.m8n8.x2.shared.b16 {%0,%1}, [%2];"
                 : "=r"(b[0]), "=r"(b[1]) : "r"(addr));
}
__device__ __forceinline__ void mma16816(float* d, const uint32_t* a, const uint32_t* b) {
    asm volatile("mma.sync.aligned.m16n8k16.row.col.f32.bf16.bf16.f32 "
                 "{%0,%1,%2,%3},{%4,%5,%6,%7},{%8,%9},{%0,%1,%2,%3};"
                 : "+f"(d[0]), "+f"(d[1]), "+f"(d[2]), "+f"(d[3])
                 : "r"(a[0]), "r"(a[1]), "r"(a[2]), "r"(a[3]), "r"(b[0]), "r"(b[1]));
}

// ===== FMA2 GEMM (proven): C = A @ W^T + bias, tile 64x128 =====
__global__ __launch_bounds__(256) void gemm2_tn(
    const float* __restrict__ A, const float* __restrict__ W,
    const float* __restrict__ bias, float* __restrict__ C, int K, int lda, int ldw, int ldc)
{
    __shared__ __align__(16) ULL smu2[2 * 64 * 33];
    ULL* As2 = smu2; ULL* Ws2 = smu2 + 64 * 33;
    const int tid = threadIdx.x, tx = tid & 15, ty = tid >> 4;
    const int m0 = blockIdx.y * 64, n0 = blockIdx.x * 128;
    ULL acc[4][4];
#pragma unroll
    for (int r = 0; r < 4; r++)
#pragma unroll
        for (int q = 0; q < 4; q++) acc[r][q] = 0ULL;
    for (int k0 = 0; k0 < K; k0 += 32) {
        for (int i = tid; i < 2048; i += 256) {
            int m = i >> 5, k = i & 31;
            float v = A[(size_t)(m0 + m) * lda + k0 + k];
            ((float2*)As2)[m * 33 + k] = make_float2(v, v);
        }
        for (int i = tid; i < 2048; i += 256) {
            int pc = i >> 5, k = i & 31;
            int n_lo = n0 + (pc >> 4) * 32 + (pc & 15);
            ((float2*)Ws2)[pc * 33 + k] = make_float2(W[(size_t)n_lo * ldw + k0 + k], W[(size_t)(n_lo + 16) * ldw + k0 + k]);
        }
        __syncthreads();
#pragma unroll 8
        for (int k = 0; k < 32; k++) {
            ULL a0 = As2[ty*33+k], a1 = As2[(ty+16)*33+k], a2 = As2[(ty+32)*33+k], a3 = As2[(ty+48)*33+k];
            ULL w0 = Ws2[tx*33+k], w1 = Ws2[(16+tx)*33+k], w2 = Ws2[(32+tx)*33+k], w3 = Ws2[(48+tx)*33+k];
            fma2(acc[0][0],w0,a0); fma2(acc[0][1],w1,a0); fma2(acc[0][2],w2,a0); fma2(acc[0][3],w3,a0);
            fma2(acc[1][0],w0,a1); fma2(acc[1][1],w1,a1); fma2(acc[1][2],w2,a1); fma2(acc[1][3],w3,a1);
            fma2(acc[2][0],w0,a2); fma2(acc[2][1],w1,a2); fma2(acc[2][2],w2,a2); fma2(acc[2][3],w3,a2);
            fma2(acc[3][0],w0,a3); fma2(acc[3][1],w1,a3); fma2(acc[3][2],w2,a3); fma2(acc[3][3],w3,a3);
        }
        __syncthreads();
    }
#pragma unroll
    for (int r = 0; r < 4; r++) {
        int m = m0 + ty + 16 * r;
#pragma unroll
        for (int q = 0; q < 4; q++) {
            float2 v = unpack2(acc[r][q]);
            int n_lo = n0 + q * 32 + tx;
            C[(size_t)m * ldc + n_lo] = v.x + bias[n_lo];
            C[(size_t)m * ldc + n_lo + 16] = v.y + bias[n_lo + 16];
        }
    }
}

// ===== persistent encoder recurrence (proven, unchanged) =====
#define WS_PITCH 1028
#define XS_PITCH 68
__global__ __launch_bounds__(256, 1) void enc_recur_kernel(
    const float* __restrict__ gi, long long gi_t_stride, long long gi_b_stride,
    const float* __restrict__ Whh, const float* __restrict__ bhh, float* __restrict__ hseq)
{
    extern __shared__ float sm[];
    float* ws = sm; float* xs = sm + 24 * WS_PITCH;
    const int tid = threadIdx.x, c = tid & 7, bq = tid >> 3;
    const int jb = blockIdx.x * 8, b0 = 2 * bq, b1 = b0 + 1, j = jb + c;
    for (int i = tid; i < 24 * 256; i += 256) {
        int r = i >> 8, kg = i & 255;
        int wr = (r >> 3) * H + jb + (r & 7);
        *(float4*)(ws + r * WS_PITCH + kg * 4) = *(const float4*)(Whh + (size_t)wr * H + kg * 4);
    }
    const float br = bhh[j], bz = bhh[H + j], bn = bhh[2 * H + j];
    __syncthreads();
    for (int t = 0; t < TIN; t++) {
        float ar0=0.f,ar1=0.f,az0=0.f,az1=0.f,an0=0.f,an1=0.f;
        const float* hprev = hseq + (size_t)(t - 1) * BH;
        if (t > 0) {
            for (int k0 = 0; k0 < H; k0 += 64) {
                for (int i = tid; i < 1024; i += 256) {
                    int b = i >> 4, kg = i & 15;
                    *(float4*)(xs + b * XS_PITCH + kg * 4) = *(const float4*)(hprev + (size_t)b * H + k0 + kg * 4);
                }
                __syncthreads();
#pragma unroll
                for (int kk = 0; kk < 64; kk += 4) {
                    float4 x0 = *(const float4*)(xs + b0 * XS_PITCH + kk);
                    float4 x1 = *(const float4*)(xs + b1 * XS_PITCH + kk);
                    float4 w0 = *(const float4*)(ws + c * WS_PITCH + k0 + kk);
                    float4 w1 = *(const float4*)(ws + (8 + c) * WS_PITCH + k0 + kk);
                    float4 w2 = *(const float4*)(ws + (16 + c) * WS_PITCH + k0 + kk);
                    ar0=fmaf(w0.x,x0.x,ar0); ar0=fmaf(w0.y,x0.y,ar0); ar0=fmaf(w0.z,x0.z,ar0); ar0=fmaf(w0.w,x0.w,ar0);
                    ar1=fmaf(w0.x,x1.x,ar1); ar1=fmaf(w0.y,x1.y,ar1); ar1=fmaf(w0.z,x1.z,ar1); ar1=fmaf(w0.w,x1.w,ar1);
                    az0=fmaf(w1.x,x0.x,az0); az0=fmaf(w1.y,x0.y,az0); az0=fmaf(w1.z,x0.z,az0); az0=fmaf(w1.w,x0.w,az0);
                    az1=fmaf(w1.x,x1.x,az1); az1=fmaf(w1.y,x1.y,az1); az1=fmaf(w1.z,x1.z,az1); az1=fmaf(w1.w,x1.w,az1);
                    an0=fmaf(w2.x,x0.x,an0); an0=fmaf(w2.y,x0.y,an0); an0=fmaf(w2.z,x0.z,an0); an0=fmaf(w2.w,x0.w,an0);
                    an1=fmaf(w2.x,x1.x,an1); an1=fmaf(w2.y,x1.y,an1); an1=fmaf(w2.z,x1.z,an1); an1=fmaf(w2.w,x1.w,an1);
                }
                __syncthreads();
            }
        }
        const float* gr0 = gi + (size_t)b0 * gi_b_stride + (size_t)t * gi_t_stride;
        const float* gr1 = gi + (size_t)b1 * gi_b_stride + (size_t)t * gi_t_stride;
        float* hout = hseq + (size_t)t * BH;
        float hp0 = (t > 0) ? hprev[(size_t)b0 * H + j] : 0.f;
        float hp1 = (t > 0) ? hprev[(size_t)b1 * H + j] : 0.f;
        {
            float r = sigmoidf_(gr0[j] + ar0 + br);
            float z = sigmoidf_(gr0[H + j] + az0 + bz);
            float n = tanhf(gr0[2 * H + j] + r * (an0 + bn));
            hout[(size_t)b0 * H + j] = (1.f - z) * n + z * hp0;
        }
        {
            float r = sigmoidf_(gr1[j] + ar1 + br);
            float z = sigmoidf_(gr1[H + j] + az1 + bz);
            float n = tanhf(gr1[2 * H + j] + r * (an1 + bn));
            hout[(size_t)b1 * H + j] = (1.f - z) * n + z * hp1;
        }
        grid_sync();
    }
}

// ===== generic 3-way bf16 split =====
__global__ __launch_bounds__(256) void split_w_kernel(
    const float* __restrict__ W, bf16* __restrict__ Wh, bf16* __restrict__ Wm,
    bf16* __restrict__ Wl, size_t n)
{
    for (size_t i = (size_t)blockIdx.x * 256 + threadIdx.x; i < n; i += (size_t)gridDim.x * 256) {
        float v = W[i];
        bf16 h = __float2bfloat16(v); float r1 = v - __bfloat162float(h);
        bf16 m = __float2bfloat16(r1);
        Wh[i] = h; Wm[i] = m; Wl[i] = __float2bfloat16(r1 - __bfloat162float(m));
    }
}

// ===== embed gather + split (per step) =====
__global__ __launch_bounds__(256) void embsplit(const float* __restrict__ embed, int s) {
    const int b = blockIdx.x;
    __shared__ int tok;
    if (threadIdx.x == 0) tok = (s == 0) ? 0 : (V - 1 - (int)(g_keys[b] & 0x7FFFULL));
    __syncthreads();
    for (int k = threadIdx.x; k < H; k += 256) {
        float v = embed[(size_t)tok * H + k];
        bf16 h = __float2bfloat16(v); float r1 = v - __bfloat162float(h);
        bf16 m = __float2bfloat16(r1);
        size_t idx = (size_t)b * H + k;
        g_xe[idx] = h; g_xe[BH + idx] = m; g_xe[2 * BH + idx] = __float2bfloat16(r1 - __bfloat162float(m));
    }
}

// ===== GRU dual GEMM on HMMA: Ygi = X@Wih^T, Ygh = Hst@Whh^T (M=64, N=3072, K=1024) =====
#define GP 40
__global__ __launch_bounds__(256) void mma_gemm(
    const bf16* __restrict__ xs3, const bf16* __restrict__ hs3,
    const bf16* __restrict__ Wih3, const bf16* __restrict__ Whh3)
{
    __shared__ __align__(16) bf16 Asm[3][64][GP];
    __shared__ __align__(16) bf16 Wsm[3][64][GP];
    const int tid = threadIdx.x, lane = tid & 31, warp = tid >> 5;
    const int wm = warp >> 2, wn = warp & 3;
    const int n0 = blockIdx.x * 64;
    const int mat = blockIdx.y;
    const bf16* Asrc[3];
    const bf16* Wsrc[3];
    const size_t WS = (size_t)H3 * H;
    if (mat == 0) {
        Asrc[0] = xs3; Asrc[1] = xs3 + BH; Asrc[2] = xs3 + 2 * BH;
        Wsrc[0] = Wih3; Wsrc[1] = Wih3 + WS; Wsrc[2] = Wih3 + 2 * WS;
    } else {
        Asrc[0] = hs3; Asrc[1] = hs3 + BH; Asrc[2] = hs3 + 2 * BH;
        Wsrc[0] = Whh3; Wsrc[1] = Whh3 + WS; Wsrc[2] = Whh3 + 2 * WS;
    }
    float* Y = mat ? g_Ygh : g_Ygi;

    const int row = tid >> 2, q = tid & 3;
    uint4 pa[3], pw[3];
#pragma unroll
    for (int sp = 0; sp < 3; sp++) {
        pa[sp] = *(const uint4*)(Asrc[sp] + (size_t)row * H + q * 8);
        pw[sp] = *(const uint4*)(Wsrc[sp] + (size_t)(n0 + row) * H + q * 8);
    }
    float acc[2][2][4];
#pragma unroll
    for (int mt = 0; mt < 2; mt++)
#pragma unroll
        for (int nt = 0; nt < 2; nt++)
#pragma unroll
            for (int r = 0; r < 4; r++) acc[mt][nt][r] = 0.f;

    for (int c = 0; c < 32; c++) {
        __syncthreads();
#pragma unroll
        for (int sp = 0; sp < 3; sp++) {
            *(uint4*)(&Asm[sp][row][q * 8]) = pa[sp];
            *(uint4*)(&Wsm[sp][row][q * 8]) = pw[sp];
        }
        __syncthreads();
        if (c < 31) {
            int k0 = (c + 1) * 32;
#pragma unroll
            for (int sp = 0; sp < 3; sp++) {
                pa[sp] = *(const uint4*)(Asrc[sp] + (size_t)row * H + k0 + q * 8);
                pw[sp] = *(const uint4*)(Wsrc[sp] + (size_t)(n0 + row) * H + k0 + q * 8);
            }
        }
#pragma unroll
        for (int k16 = 0; k16 < 2; k16++) {
            uint32_t af[3][2][4];
#pragma unroll
            for (int sp = 0; sp < 3; sp++)
#pragma unroll
                for (int mt = 0; mt < 2; mt++)
                    ldmA(af[sp][mt], smem_u32(&Asm[sp][wm * 32 + mt * 16 + (lane & 15)][k16 * 16 + (lane >> 4) * 8]));
#pragma unroll
            for (int nt = 0; nt < 2; nt++) {
                uint32_t bfr[3][2];
#pragma unroll
                for (int sp = 0; sp < 3; sp++)
                    ldmB(bfr[sp], smem_u32(&Wsm[sp][wn * 16 + nt * 8 + (lane & 7)][k16 * 16 + ((lane >> 3) & 1) * 8]));
#pragma unroll
                for (int mt = 0; mt < 2; mt++) {
                    mma16816(acc[mt][nt], af[0][mt], bfr[0]);
                    mma16816(acc[mt][nt], af[0][mt], bfr[1]);
                    mma16816(acc[mt][nt], af[1][mt], bfr[0]);
                    mma16816(acc[mt][nt], af[0][mt], bfr[2]);
                    mma16816(acc[mt][nt], af[1][mt], bfr[1]);
                    mma16816(acc[mt][nt], af[2][mt], bfr[0]);
                }
            }
        }
    }
#pragma unroll
    for (int mt = 0; mt < 2; mt++)
#pragma unroll
        for (int half = 0; half < 2; half++) {
            int m = wm * 32 + mt * 16 + half * 8 + (lane >> 2);
#pragma unroll
            for (int nt = 0; nt < 2; nt++) {
                int n = n0 + wn * 16 + nt * 8 + (lane & 3) * 2;
                Y[(size_t)m * H3 + n]     = acc[mt][nt][half * 2 + 0];
                Y[(size_t)m * H3 + n + 1] = acc[mt][nt][half * 2 + 1];
            }
        }
}

// ===== GRU gate epilogue (fp32 exact recurrence; emits bf16 splits of h) =====
__global__ __launch_bounds__(1024) void gru_epi(
    const float* __restrict__ bih, const float* __restrict__ bhh,
    const float* __restrict__ hin, float* __restrict__ hout,
    bf16* __restrict__ sp3, float* __restrict__ cat_aux)
{
    const int b = blockIdx.x, j = threadIdx.x;
    const size_t rb = (size_t)b * H3;
    float gi_r = g_Ygi[rb + j], gi_z = g_Ygi[rb + H + j], gi_n = g_Ygi[rb + 2 * H + j];
    float gh_r = g_Ygh[rb + j], gh_z = g_Ygh[rb + H + j], gh_n = g_Ygh[rb + 2 * H + j];
    float hp = hin[(size_t)b * H + j];
    float r = sigmoidf_((gi_r + bih[j]) + (gh_r + bhh[j]));
    float z = sigmoidf_((gi_z + bih[H + j]) + (gh_z + bhh[H + j]));
    float n = tanhf((gi_n + bih[2 * H + j]) + r * (gh_n + bhh[2 * H + j]));
    float h = (1.f - z) * n + z * hp;
    size_t idx = (size_t)b * H + j;
    hout[idx] = h;
    bf16 hv = __float2bfloat16(h); float r1 = h - __bfloat162float(hv);
    bf16 mv = __float2bfloat16(r1);
    sp3[idx] = hv; sp3[BH + idx] = mv; sp3[2 * BH + idx] = __float2bfloat16(r1 - __bfloat162float(mv));
    if (cat_aux) cat_aux[(size_t)b * 2 * H + H + j] = h;
}

// ===== linear (proven; optional 3-way split of result) =====
__global__ __launch_bounds__(256) void lin_kernel(
    const float* __restrict__ Wt, int wstride, const float* __restrict__ bias,
    const float* __restrict__ X, int xstride, int K, float* __restrict__ Y,
    int reset_keys, int write_split)
{
    __shared__ float xs[64 * XS_PITCH], ws[4 * XS_PITCH];
    const int tid = threadIdx.x, c = tid & 3, b = tid >> 2;
    const int jb = blockIdx.x * 4;
    if (reset_keys && blockIdx.x == 0 && tid < B) g_keys[tid] = 0ULL;
    float a = 0.f;
    for (int k0 = 0; k0 < K; k0 += 64) {
        for (int i = tid; i < 1024; i += 256) {
            int bb = i >> 4, kg = i & 15;
            *(float4*)(xs + bb * XS_PITCH + kg * 4) = *(const float4*)(X + (size_t)bb * xstride + k0 + kg * 4);
        }
        if (tid < 64) {
            int r = tid >> 4, kg = tid & 15;
            *(float4*)(ws + r * XS_PITCH + kg * 4) = *(const float4*)(Wt + (size_t)(jb + r) * wstride + k0 + kg * 4);
        }
        __syncthreads();
#pragma unroll
        for (int kk = 0; kk < 64; kk += 4) {
            float4 xv = *(const float4*)(xs + b * XS_PITCH + kk);
            float4 wv = *(const float4*)(ws + c * XS_PITCH + kk);
            a = fmaf(wv.x, xv.x, a); a = fmaf(wv.y, xv.y, a);
            a = fmaf(wv.z, xv.z, a); a = fmaf(wv.w, xv.w, a);
        }
        __syncthreads();
    }
    float v = a + bias[jb + c];
    size_t idx = (size_t)b * H + jb + c;
    Y[idx] = v;
    if (write_split) {
        bf16 hv = __float2bfloat16(v); float r1 = v - __bfloat162float(hv);
        bf16 mv = __float2bfloat16(r1);
        g_ch[idx] = hv; g_cm[idx] = mv; g_cl[idx] = __float2bfloat16(r1 - __bfloat162float(mv));
    }
}

// ===== attention (proven, unchanged) =====
__global__ __launch_bounds__(1024) void attn_kernel(
    const float* __restrict__ q, const float* __restrict__ enc,
    float* __restrict__ cat, float* __restrict__ attn_out, int s)
{
    __shared__ float qs[H], wv[TIN], red[256];
    const int b = blockIdx.x, tid = threadIdx.x;
    qs[tid] = q[(size_t)b * H + tid];
    __syncthreads();
    const int warp = tid >> 5, lane = tid & 31;
    for (int t = warp; t < TIN; t += 32) {
        const float* e = enc + (size_t)(t * B + b) * H;
        float sacc = 0.f;
#pragma unroll 4
        for (int k = lane; k < H; k += 32) sacc = fmaf(qs[k], e[k], sacc);
        for (int o = 16; o; o >>= 1) sacc += __shfl_xor_sync(0xffffffffu, sacc, o);
        if (!lane) wv[t] = sacc;
    }
    __syncthreads();
    float v = 0.f, ev = 0.f;
    if (tid < 256) { v = wv[tid]; red[tid] = v; }
    __syncthreads();
    for (int st = 128; st; st >>= 1) { if (tid < st) red[tid] = fmaxf(red[tid], red[tid + st]); __syncthreads(); }
    float mx = red[0]; __syncthreads();
    if (tid < 256) { ev = expf(v - mx); red[tid] = ev; }
    __syncthreads();
    for (int st = 128; st; st >>= 1) { if (tid < st) red[tid] += red[tid + st]; __syncthreads(); }
    if (tid < 256) {
        float aw = ev / red[0];
        wv[tid] = aw;
        attn_out[((size_t)b * TIN + tid) * TGT + s] = aw;
    }
    __syncthreads();
    {
        int k = tid; float sacc = 0.f;
        for (int t = 0; t < TIN; t++) sacc = fmaf(wv[t], enc[(size_t)(t * B + b) * H + k], sacc);
        cat[(size_t)b * 2 * H + k] = sacc;
    }
}

// ===== fc on HMMA (proven R12, unchanged) =====
#define AP 40
__global__ __launch_bounds__(256) void fc_mma(
    const bf16* __restrict__ Wh, const bf16* __restrict__ Wm,
    const bf16* __restrict__ Wl, const float* __restrict__ bfc,
    float* __restrict__ out, int s)
{
    __shared__ __align__(16) bf16 Asm[3][64][AP];
    __shared__ __align__(16) bf16 Wsm[3][128][AP];
    __shared__ ULL skeys[B];
    const int tid = threadIdx.x, lane = tid & 31, warp = tid >> 5;
    const int wm = warp >> 2, wn = warp & 3;
    const int n0 = blockIdx.x * 128;
    if (tid < B) skeys[tid] = 0ULL;
    const bf16* Asrc[3] = { g_ch, g_cm, g_cl };
    const bf16* Wsrc[3] = { Wh, Wm, Wl };
    const int arow = tid >> 2, aq = tid & 3;
    uint4 pa[3], pw[3][2];
#pragma unroll
    for (int sp = 0; sp < 3; sp++) {
        pa[sp] = *(const uint4*)(Asrc[sp] + (size_t)arow * H + aq * 8);
#pragma unroll
        for (int t = 0; t < 2; t++) {
            int i = tid + t * 256, row = i >> 2, q = i & 3;
            pw[sp][t] = *(const uint4*)(Wsrc[sp] + (size_t)(n0 + row) * H + q * 8);
        }
    }
    float acc[2][4][4];
#pragma unroll
    for (int mt = 0; mt < 2; mt++)
#pragma unroll
        for (int nt = 0; nt < 4; nt++)
#pragma unroll
            for (int r = 0; r < 4; r++) acc[mt][nt][r] = 0.f;
    for (int c = 0; c < 32; c++) {
        __syncthreads();
#pragma unroll
        for (int sp = 0; sp < 3; sp++) {
            *(uint4*)(&Asm[sp][arow][aq * 8]) = pa[sp];
#pragma unroll
            for (int t = 0; t < 2; t++) {
                int i = tid + t * 256, row = i >> 2, q = i & 3;
                *(uint4*)(&Wsm[sp][row][q * 8]) = pw[sp][t];
            }
        }
        __syncthreads();
        if (c < 31) {
            int k0 = (c + 1) * 32;
#pragma unroll
            for (int sp = 0; sp < 3; sp++) {
                pa[sp] = *(const uint4*)(Asrc[sp] + (size_t)arow * H + k0 + aq * 8);
#pragma unroll
                for (int t = 0; t < 2; t++) {
                    int i = tid + t * 256, row = i >> 2, q = i & 3;
                    pw[sp][t] = *(const uint4*)(Wsrc[sp] + (size_t)(n0 + row) * H + k0 + q * 8);
                }
            }
        }
#pragma unroll
        for (int k16 = 0; k16 < 2; k16++) {
            uint32_t af[3][2][4];
#pragma unroll
            for (int sp = 0; sp < 3; sp++)
#pragma unroll
                for (int mt = 0; mt < 2; mt++)
                    ldmA(af[sp][mt], smem_u32(&Asm[sp][wm * 32 + mt * 16 + (lane & 15)][k16 * 16 + (lane >> 4) * 8]));
#pragma unroll
            for (int nt = 0; nt < 4; nt++) {
                uint32_t bfr[3][2];
#pragma unroll
                for (int sp = 0; sp < 3; sp++)
                    ldmB(bfr[sp], smem_u32(&Wsm[sp][wn * 32 + nt * 8 + (lane & 7)][k16 * 16 + ((lane >> 3) & 1) * 8]));
#pragma unroll
                for (int mt = 0; mt < 2; mt++) {
                    mma16816(acc[mt][nt], af[0][mt], bfr[0]);
                    mma16816(acc[mt][nt], af[0][mt], bfr[1]);
                    mma16816(acc[mt][nt], af[1][mt], bfr[0]);
                    mma16816(acc[mt][nt], af[0][mt], bfr[2]);
                    mma16816(acc[mt][nt], af[1][mt], bfr[1]);
                    mma16816(acc[mt][nt], af[2][mt], bfr[0]);
                }
            }
        }
    }
#pragma unroll
    for (int mt = 0; mt < 2; mt++)
#pragma unroll
        for (int half = 0; half < 2; half++) {
            int m = wm * 32 + mt * 16 + half * 8 + (lane >> 2);
            float* orow = out + ((size_t)m * TGT + s) * V;
            ULL rmax = 0ULL;
#pragma unroll
            for (int nt = 0; nt < 4; nt++) {
                int n = n0 + wn * 32 + nt * 8 + (lane & 3) * 2;
                float v0 = acc[mt][nt][half * 2 + 0] + bfc[n];
                float v1 = acc[mt][nt][half * 2 + 1] + bfc[n + 1];
                *(float2*)(orow + n) = make_float2(v0, v1);
                ULL k0b = ((ULL)ord32(v0) << 15) | (ULL)(V - 1 - n);
                ULL k1b = ((ULL)ord32(v1) << 15) | (ULL)(V - 2 - n);
                if (k0b > rmax) rmax = k0b;
                if (k1b > rmax) rmax = k1b;
            }
            atomicMax(&skeys[m], rmax);
        }
    __syncthreads();
    if (tid < B) atomicMax(&g_keys[tid], skeys[tid]);
}

// ===== host =====
extern "C" void kernel_launch(void* const* d_in, const int* in_sizes, int n_in,
                              void* d_out_, int out_size) {
    const float* x = (const float*)d_in[0];
    const float* embed = (const float*)d_in[1];
    const float* eWih0 = (const float*)d_in[2];  const float* eWhh0 = (const float*)d_in[3];
    const float* ebih0 = (const float*)d_in[4];  const float* ebhh0 = (const float*)d_in[5];
    const float* eWih1 = (const float*)d_in[6];  const float* eWhh1 = (const float*)d_in[7];
    const float* ebih1 = (const float*)d_in[8];  const float* ebhh1 = (const float*)d_in[9];
    const float* dWih0 = (const float*)d_in[10]; const float* dWhh0 = (const float*)d_in[11];
    const float* dbih0 = (const float*)d_in[12]; const float* dbhh0 = (const float*)d_in[13];
    const float* dWih1 = (const float*)d_in[14]; const float* dWhh1 = (const float*)d_in[15];
    const float* dbih1 = (const float*)d_in[16]; const float* dbhh1 = (const float*)d_in[17];
    const float* Wq = (const float*)d_in[18];    const float* bq = (const float*)d_in[19];
    const float* Wc = (const float*)d_in[20];    const float* bc = (const float*)d_in[21];
    const float* Wfc = (const float*)d_in[22];   const float* bfc = (const float*)d_in[23];
    float* out = (float*)d_out_;
    const size_t HID_OFF = (size_t)B * TGT * V;
    const size_t ATTN_OFF = HID_OFF + (size_t)2 * BH;

    float *gi0, *gi1, *h0seq, *enc, *dh0, *dh1, *q, *cat, *comb;
    bf16 *xe, *h0s, *h1s;
    cudaGetSymbolAddress((void**)&gi0, g_gi0);
    cudaGetSymbolAddress((void**)&gi1, g_gi1);
    cudaGetSymbolAddress((void**)&h0seq, g_h0seq);
    cudaGetSymbolAddress((void**)&enc, g_enc);
    cudaGetSymbolAddress((void**)&dh0, g_dh0);
    cudaGetSymbolAddress((void**)&dh1, g_dh1);
    cudaGetSymbolAddress((void**)&q, g_q);
    cudaGetSymbolAddress((void**)&cat, g_cat);
    cudaGetSymbolAddress((void**)&comb, g_comb);
    cudaGetSymbolAddress((void**)&xe, g_xe);
    cudaGetSymbolAddress((void**)&h0s, g_h0s);
    cudaGetSymbolAddress((void**)&h1s, g_h1s);
    bf16* Wfh = (bf16*)gi0;
    bf16* Wfm = Wfh + (size_t)V * H;
    bf16* Wfl = Wfm + (size_t)V * H;
    const size_t WS = (size_t)H3 * H;
    bf16* wsp = (bf16*)gi1;   // [Wih0 h/m/l][Whh0 h/m/l][Wih1 h/m/l][Whh1 h/m/l]
    bf16* Wih0s = wsp;
    bf16* Whh0s = wsp + 3 * WS;
    bf16* Wih1s = wsp + 6 * WS;
    bf16* Whh1s = wsp + 9 * WS;

    const int ENC_SMEM = (24 * WS_PITCH + 64 * XS_PITCH) * (int)sizeof(float);
    cudaFuncSetAttribute(enc_recur_kernel, cudaFuncAttributeMaxDynamicSharedMemorySize, ENC_SMEM);

    // ---- encoder ----
    gemm2_tn<<<dim3(H3/128, (B*TIN)/64), 256>>>(x, eWih0, ebih0, gi0, F, F, F, H3);
    enc_recur_kernel<<<128, 256, ENC_SMEM>>>(gi0, (long long)H3, (long long)TIN * H3, eWhh0, ebhh0, h0seq);
    gemm2_tn<<<dim3(H3/128, (B*TIN)/64), 256>>>(h0seq, eWih1, ebih1, gi1, H, H, H, H3);
    enc_recur_kernel<<<128, 256, ENC_SMEM>>>(gi1, (long long)B * H3, (long long)H3, eWhh1, ebhh1, enc);

    // ---- one-time splits (gi0/gi1 are free after the encoder) ----
    split_w_kernel<<<1024, 256>>>(Wfc, Wfh, Wfm, Wfl, (size_t)V * H);
    split_w_kernel<<<512, 256>>>(dWih0, Wih0s, Wih0s + WS, Wih0s + 2 * WS, WS);
    split_w_kernel<<<512, 256>>>(dWhh0, Whh0s, Whh0s + WS, Whh0s + 2 * WS, WS);
    split_w_kernel<<<512, 256>>>(dWih1, Wih1s, Wih1s + WS, Wih1s + 2 * WS, WS);
    split_w_kernel<<<512, 256>>>(dWhh1, Whh1s, Whh1s + WS, Whh1s + 2 * WS, WS);
    // initial hidden splits into parity slot 1 (read when s=0)
    split_w_kernel<<<256, 256>>>(h0seq + (size_t)(TIN - 1) * BH,
        h0s + 3 * BH, h0s + 4 * BH, h0s + 5 * BH, (size_t)BH);
    split_w_kernel<<<256, 256>>>(enc + (size_t)(TIN - 1) * BH,
        h1s + 3 * BH, h1s + 4 * BH, h1s + 5 * BH, (size_t)BH);

    // ---- decoder ----
    for (int s = 0; s < TGT; s++) {
        const int p0 = s & 1, p1 = (s + 1) & 1;
        const float* h0in = s ? (dh0 + (size_t)p1 * BH) : (h0seq + (size_t)(TIN - 1) * BH);
        const float* h1in = s ? (dh1 + (size_t)p1 * BH) : (enc + (size_t)(TIN - 1) * BH);
        float* h0out = dh0 + (size_t)p0 * BH;
        float* h1out = dh1 + (size_t)p0 * BH;

        embsplit<<<B, 256>>>(embed, s);
        mma_gemm<<<dim3(H3/64, 2), 256>>>(xe, h0s + (size_t)p1 * 3 * BH, Wih0s, Whh0s);
        gru_epi<<<B, 1024>>>(dbih0, dbhh0, h0in, h0out, h0s + (size_t)p0 * 3 * BH, nullptr);
        mma_gemm<<<dim3(H3/64, 2), 256>>>(h0s + (size_t)p0 * 3 * BH, h1s + (size_t)p1 * 3 * BH, Wih1s, Whh1s);
        gru_epi<<<B, 1024>>>(dbih1, dbhh1, h1in, h1out, h1s + (size_t)p0 * 3 * BH, cat);
        lin_kernel<<<256, 256>>>(Wq, H, bq, h1out, H, H, q, 0, 0);
        attn_kernel<<<B, 1024>>>(q, enc, cat, out + ATTN_OFF, s);
        lin_kernel<<<256, 256>>>(Wc, 2 * H, bc, cat, 2 * H, 2 * H, comb, 1, 1);
        fc_mma<<<V / 128, 256>>>(Wfh, Wfm, Wfl, bfc, out, s);
    }
    cudaMemcpyAsync(out + HID_OFF,      dh0 + BH, (size_t)BH * sizeof(float), cudaMemcpyDeviceToDevice);
    cudaMemcpyAsync(out + HID_OFF + BH, dh1 + BH, (size_t)BH * sizeof(float), cudaMemcpyDeviceToDevice);
}

// round 15
// speedup vs baseline: 1.3879x; 1.0148x over previous
#include <cuda_runtime.h>
#include <cuda_bf16.h>
#include <cfloat>
#include <cstddef>
#include <cstdint>

#define B 64
#define TIN 256
#define F 64
#define H 1024
#define H3 3072
#define TGT 64
#define V 32000
#define BH (B*H)
typedef unsigned long long ULL;
typedef unsigned int uint;
typedef __nv_bfloat16 bf16;

__device__ float g_gi0[(size_t)TIN * B * H3];   // reused: Wfc bf16 splits
__device__ float g_gi1[(size_t)TIN * B * H3];   // reused: GRU/Wq/Wc bf16 splits
__device__ float g_h0seq[(size_t)TIN * BH];
__device__ float g_enc[(size_t)TIN * BH];
__device__ float g_dh0[2 * BH];
__device__ float g_dh1[2 * BH];
__device__ float g_q[BH];
__device__ float g_cat[B * 2 * H];
__device__ float g_comb[BH];
__device__ float g_Ygi[(size_t)B * H3];
__device__ float g_Ygh[(size_t)B * H3];
__device__ bf16 g_ch[BH], g_cm[BH], g_cl[BH];
__device__ bf16 g_xe[3 * BH];
__device__ bf16 g_h0s[2 * 3 * BH];
__device__ bf16 g_h1s[2 * 3 * BH];
__device__ bf16 g_cats[3 * B * 2 * H];
__device__ ULL g_keys[B];
__device__ unsigned long long g_bar64;

__device__ __forceinline__ void grid_sync() {
    __syncthreads();
    if (threadIdx.x == 0) {
        __threadfence();
        unsigned long long old = atomicAdd(&g_bar64, 1ULL);
        unsigned gen = (unsigned)(old >> 32);
        if ((unsigned)old == gridDim.x - 1)
            atomicAdd(&g_bar64, (1ULL << 32) - (unsigned long long)gridDim.x);
        else
            while ((unsigned)((*(volatile unsigned long long*)&g_bar64) >> 32) == gen) { }
        __threadfence();
    }
    __syncthreads();
}
__device__ __forceinline__ float sigmoidf_(float x) { return 1.f / (1.f + expf(-x)); }
__device__ __forceinline__ void fma2(ULL& d, ULL a, ULL b) {
    asm("fma.rn.f32x2 %0, %1, %2, %0;" : "+l"(d) : "l"(a), "l"(b));
}
__device__ __forceinline__ float2 unpack2(ULL v) {
    float2 r; asm("mov.b64 {%0, %1}, %2;" : "=f"(r.x), "=f"(r.y) : "l"(v)); return r;
}
__device__ __forceinline__ uint ord32(float f) {
    uint u = __float_as_uint(f);
    return u ^ ((u >> 31) ? 0xFFFFFFFFu : 0x80000000u);
}
__device__ __forceinline__ uint32_t smem_u32(const void* p) {
    uint32_t a;
    asm("{ .reg .u64 t; cvta.to.shared.u64 t, %1; cvt.u32.u64 %0, t; }" : "=r"(a) : "l"(p));
    return a;
}
__device__ __forceinline__ void ldmA(uint32_t* a, uint32_t addr) {
    asm volatile("ldmatrix.sync.aligned.m8n8.x4.shared.b16 {%0,%1,%2,%3}, [%4];"
                 : "=r"(a[0]), "=r"(a[1]), "=r"(a[2]), "=r"(a[3]) : "r"(addr));
}
__device__ __forceinline__ void ldmB(uint32_t* b, uint32_t addr) {
    asm volatile("ldmatrix.sync.aligned.m8n8.x2.shared.b16 {%0,%1}, [%2];"
                 : "=r"(b[0]), "=r"(b[1]) : "r"(addr));
}
__device__ __forceinline__ void mma16816(float* d, const uint32_t* a, const uint32_t* b) {
    asm volatile("mma.sync.aligned.m16n8k16.row.col.f32.bf16.bf16.f32 "
                 "{%0,%1,%2,%3},{%4,%5,%6,%7},{%8,%9},{%0,%1,%2,%3};"
                 : "+f"(d[0]), "+f"(d[1]), "+f"(d[2]), "+f"(d[3])
                 : "r"(a[0]), "r"(a[1]), "r"(a[2]), "r"(a[3]), "r"(b[0]), "r"(b[1]));
}
__device__ __forceinline__ void split3(float v, bf16& h, bf16& m, bf16& l) {
    h = __float2bfloat16(v); float r1 = v - __bfloat162float(h);
    m = __float2bfloat16(r1);
    l = __float2bfloat16(r1 - __bfloat162float(m));
}

// ===== FMA2 GEMM (proven): C = A @ W^T + bias, tile 64x128 =====
__global__ __launch_bounds__(256) void gemm2_tn(
    const float* __restrict__ A, const float* __restrict__ W,
    const float* __restrict__ bias, float* __restrict__ C, int K, int lda, int ldw, int ldc)
{
    __shared__ __align__(16) ULL smu2[2 * 64 * 33];
    ULL* As2 = smu2; ULL* Ws2 = smu2 + 64 * 33;
    const int tid = threadIdx.x, tx = tid & 15, ty = tid >> 4;
    const int m0 = blockIdx.y * 64, n0 = blockIdx.x * 128;
    ULL acc[4][4];
#pragma unroll
    for (int r = 0; r < 4; r++)
#pragma unroll
        for (int q = 0; q < 4; q++) acc[r][q] = 0ULL;
    for (int k0 = 0; k0 < K; k0 += 32) {
        for (int i = tid; i < 2048; i += 256) {
            int m = i >> 5, k = i & 31;
            float v = A[(size_t)(m0 + m) * lda + k0 + k];
            ((float2*)As2)[m * 33 + k] = make_float2(v, v);
        }
        for (int i = tid; i < 2048; i += 256) {
            int pc = i >> 5, k = i & 31;
            int n_lo = n0 + (pc >> 4) * 32 + (pc & 15);
            ((float2*)Ws2)[pc * 33 + k] = make_float2(W[(size_t)n_lo * ldw + k0 + k], W[(size_t)(n_lo + 16) * ldw + k0 + k]);
        }
        __syncthreads();
#pragma unroll 8
        for (int k = 0; k < 32; k++) {
            ULL a0 = As2[ty*33+k], a1 = As2[(ty+16)*33+k], a2 = As2[(ty+32)*33+k], a3 = As2[(ty+48)*33+k];
            ULL w0 = Ws2[tx*33+k], w1 = Ws2[(16+tx)*33+k], w2 = Ws2[(32+tx)*33+k], w3 = Ws2[(48+tx)*33+k];
            fma2(acc[0][0],w0,a0); fma2(acc[0][1],w1,a0); fma2(acc[0][2],w2,a0); fma2(acc[0][3],w3,a0);
            fma2(acc[1][0],w0,a1); fma2(acc[1][1],w1,a1); fma2(acc[1][2],w2,a1); fma2(acc[1][3],w3,a1);
            fma2(acc[2][0],w0,a2); fma2(acc[2][1],w1,a2); fma2(acc[2][2],w2,a2); fma2(acc[2][3],w3,a2);
            fma2(acc[3][0],w0,a3); fma2(acc[3][1],w1,a3); fma2(acc[3][2],w2,a3); fma2(acc[3][3],w3,a3);
        }
        __syncthreads();
    }
#pragma unroll
    for (int r = 0; r < 4; r++) {
        int m = m0 + ty + 16 * r;
#pragma unroll
        for (int q = 0; q < 4; q++) {
            float2 v = unpack2(acc[r][q]);
            int n_lo = n0 + q * 32 + tx;
            C[(size_t)m * ldc + n_lo] = v.x + bias[n_lo];
            C[(size_t)m * ldc + n_lo + 16] = v.y + bias[n_lo + 16];
        }
    }
}

// ===== persistent encoder recurrence (proven, unchanged) =====
#define WS_PITCH 1028
#define XS_PITCH 68
__global__ __launch_bounds__(256, 1) void enc_recur_kernel(
    const float* __restrict__ gi, long long gi_t_stride, long long gi_b_stride,
    const float* __restrict__ Whh, const float* __restrict__ bhh, float* __restrict__ hseq)
{
    extern __shared__ float sm[];
    float* ws = sm; float* xs = sm + 24 * WS_PITCH;
    const int tid = threadIdx.x, c = tid & 7, bq = tid >> 3;
    const int jb = blockIdx.x * 8, b0 = 2 * bq, b1 = b0 + 1, j = jb + c;
    for (int i = tid; i < 24 * 256; i += 256) {
        int r = i >> 8, kg = i & 255;
        int wr = (r >> 3) * H + jb + (r & 7);
        *(float4*)(ws + r * WS_PITCH + kg * 4) = *(const float4*)(Whh + (size_t)wr * H + kg * 4);
    }
    const float br = bhh[j], bz = bhh[H + j], bn = bhh[2 * H + j];
    __syncthreads();
    for (int t = 0; t < TIN; t++) {
        float ar0=0.f,ar1=0.f,az0=0.f,az1=0.f,an0=0.f,an1=0.f;
        const float* hprev = hseq + (size_t)(t - 1) * BH;
        if (t > 0) {
            for (int k0 = 0; k0 < H; k0 += 64) {
                for (int i = tid; i < 1024; i += 256) {
                    int b = i >> 4, kg = i & 15;
                    *(float4*)(xs + b * XS_PITCH + kg * 4) = *(const float4*)(hprev + (size_t)b * H + k0 + kg * 4);
                }
                __syncthreads();
#pragma unroll
                for (int kk = 0; kk < 64; kk += 4) {
                    float4 x0 = *(const float4*)(xs + b0 * XS_PITCH + kk);
                    float4 x1 = *(const float4*)(xs + b1 * XS_PITCH + kk);
                    float4 w0 = *(const float4*)(ws + c * WS_PITCH + k0 + kk);
                    float4 w1 = *(const float4*)(ws + (8 + c) * WS_PITCH + k0 + kk);
                    float4 w2 = *(const float4*)(ws + (16 + c) * WS_PITCH + k0 + kk);
                    ar0=fmaf(w0.x,x0.x,ar0); ar0=fmaf(w0.y,x0.y,ar0); ar0=fmaf(w0.z,x0.z,ar0); ar0=fmaf(w0.w,x0.w,ar0);
                    ar1=fmaf(w0.x,x1.x,ar1); ar1=fmaf(w0.y,x1.y,ar1); ar1=fmaf(w0.z,x1.z,ar1); ar1=fmaf(w0.w,x1.w,ar1);
                    az0=fmaf(w1.x,x0.x,az0); az0=fmaf(w1.y,x0.y,az0); az0=fmaf(w1.z,x0.z,az0); az0=fmaf(w1.w,x0.w,az0);
                    az1=fmaf(w1.x,x1.x,az1); az1=fmaf(w1.y,x1.y,az1); az1=fmaf(w1.z,x1.z,az1); az1=fmaf(w1.w,x1.w,az1);
                    an0=fmaf(w2.x,x0.x,an0); an0=fmaf(w2.y,x0.y,an0); an0=fmaf(w2.z,x0.z,an0); an0=fmaf(w2.w,x0.w,an0);
                    an1=fmaf(w2.x,x1.x,an1); an1=fmaf(w2.y,x1.y,an1); an1=fmaf(w2.z,x1.z,an1); an1=fmaf(w2.w,x1.w,an1);
                }
                __syncthreads();
            }
        }
        const float* gr0 = gi + (size_t)b0 * gi_b_stride + (size_t)t * gi_t_stride;
        const float* gr1 = gi + (size_t)b1 * gi_b_stride + (size_t)t * gi_t_stride;
        float* hout = hseq + (size_t)t * BH;
        float hp0 = (t > 0) ? hprev[(size_t)b0 * H + j] : 0.f;
        float hp1 = (t > 0) ? hprev[(size_t)b1 * H + j] : 0.f;
        {
            float r = sigmoidf_(gr0[j] + ar0 + br);
            float z = sigmoidf_(gr0[H + j] + az0 + bz);
            float n = tanhf(gr0[2 * H + j] + r * (an0 + bn));
            hout[(size_t)b0 * H + j] = (1.f - z) * n + z * hp0;
        }
        {
            float r = sigmoidf_(gr1[j] + ar1 + br);
            float z = sigmoidf_(gr1[H + j] + az1 + bz);
            float n = tanhf(gr1[2 * H + j] + r * (an1 + bn));
            hout[(size_t)b1 * H + j] = (1.f - z) * n + z * hp1;
        }
        grid_sync();
    }
}

// ===== generic 3-way bf16 split =====
__global__ __launch_bounds__(256) void split_w_kernel(
    const float* __restrict__ W, bf16* __restrict__ Wh, bf16* __restrict__ Wm,
    bf16* __restrict__ Wl, size_t n)
{
    for (size_t i = (size_t)blockIdx.x * 256 + threadIdx.x; i < n; i += (size_t)gridDim.x * 256) {
        bf16 h, m, l; split3(W[i], h, m, l);
        Wh[i] = h; Wm[i] = m; Wl[i] = l;
    }
}

// ===== embed gather + split (per step) =====
__global__ __launch_bounds__(256) void embsplit(const float* __restrict__ embed, int s) {
    const int b = blockIdx.x;
    __shared__ int tok;
    if (threadIdx.x == 0) tok = (s == 0) ? 0 : (V - 1 - (int)(g_keys[b] & 0x7FFFULL));
    __syncthreads();
    for (int k = threadIdx.x; k < H; k += 256) {
        bf16 h, m, l; split3(embed[(size_t)tok * H + k], h, m, l);
        size_t idx = (size_t)b * H + k;
        g_xe[idx] = h; g_xe[BH + idx] = m; g_xe[2 * BH + idx] = l;
    }
}

// ===== GRU dual GEMM on HMMA (proven R14) =====
#define GP 40
__global__ __launch_bounds__(256) void mma_gemm(
    const bf16* __restrict__ xs3, const bf16* __restrict__ hs3,
    const bf16* __restrict__ Wih3, const bf16* __restrict__ Whh3)
{
    __shared__ __align__(16) bf16 Asm[3][64][GP];
    __shared__ __align__(16) bf16 Wsm[3][64][GP];
    const int tid = threadIdx.x, lane = tid & 31, warp = tid >> 5;
    const int wm = warp >> 2, wn = warp & 3;
    const int n0 = blockIdx.x * 64;
    const int mat = blockIdx.y;
    const bf16* Asrc[3];
    const bf16* Wsrc[3];
    const size_t WS = (size_t)H3 * H;
    if (mat == 0) {
        Asrc[0] = xs3; Asrc[1] = xs3 + BH; Asrc[2] = xs3 + 2 * BH;
        Wsrc[0] = Wih3; Wsrc[1] = Wih3 + WS; Wsrc[2] = Wih3 + 2 * WS;
    } else {
        Asrc[0] = hs3; Asrc[1] = hs3 + BH; Asrc[2] = hs3 + 2 * BH;
        Wsrc[0] = Whh3; Wsrc[1] = Whh3 + WS; Wsrc[2] = Whh3 + 2 * WS;
    }
    float* Y = mat ? g_Ygh : g_Ygi;
    const int row = tid >> 2, q = tid & 3;
    uint4 pa[3], pw[3];
#pragma unroll
    for (int sp = 0; sp < 3; sp++) {
        pa[sp] = *(const uint4*)(Asrc[sp] + (size_t)row * H + q * 8);
        pw[sp] = *(const uint4*)(Wsrc[sp] + (size_t)(n0 + row) * H + q * 8);
    }
    float acc[2][2][4];
#pragma unroll
    for (int mt = 0; mt < 2; mt++)
#pragma unroll
        for (int nt = 0; nt < 2; nt++)
#pragma unroll
            for (int r = 0; r < 4; r++) acc[mt][nt][r] = 0.f;
    for (int c = 0; c < 32; c++) {
        __syncthreads();
#pragma unroll
        for (int sp = 0; sp < 3; sp++) {
            *(uint4*)(&Asm[sp][row][q * 8]) = pa[sp];
            *(uint4*)(&Wsm[sp][row][q * 8]) = pw[sp];
        }
        __syncthreads();
        if (c < 31) {
            int k0 = (c + 1) * 32;
#pragma unroll
            for (int sp = 0; sp < 3; sp++) {
                pa[sp] = *(const uint4*)(Asrc[sp] + (size_t)row * H + k0 + q * 8);
                pw[sp] = *(const uint4*)(Wsrc[sp] + (size_t)(n0 + row) * H + k0 + q * 8);
            }
        }
#pragma unroll
        for (int k16 = 0; k16 < 2; k16++) {
            uint32_t af[3][2][4];
#pragma unroll
            for (int sp = 0; sp < 3; sp++)
#pragma unroll
                for (int mt = 0; mt < 2; mt++)
                    ldmA(af[sp][mt], smem_u32(&Asm[sp][wm * 32 + mt * 16 + (lane & 15)][k16 * 16 + (lane >> 4) * 8]));
#pragma unroll
            for (int nt = 0; nt < 2; nt++) {
                uint32_t bfr[3][2];
#pragma unroll
                for (int sp = 0; sp < 3; sp++)
                    ldmB(bfr[sp], smem_u32(&Wsm[sp][wn * 16 + nt * 8 + (lane & 7)][k16 * 16 + ((lane >> 3) & 1) * 8]));
#pragma unroll
                for (int mt = 0; mt < 2; mt++) {
                    mma16816(acc[mt][nt], af[0][mt], bfr[0]);
                    mma16816(acc[mt][nt], af[0][mt], bfr[1]);
                    mma16816(acc[mt][nt], af[1][mt], bfr[0]);
                    mma16816(acc[mt][nt], af[0][mt], bfr[2]);
                    mma16816(acc[mt][nt], af[1][mt], bfr[1]);
                    mma16816(acc[mt][nt], af[2][mt], bfr[0]);
                }
            }
        }
    }
#pragma unroll
    for (int mt = 0; mt < 2; mt++)
#pragma unroll
        for (int half = 0; half < 2; half++) {
            int m = wm * 32 + mt * 16 + half * 8 + (lane >> 2);
#pragma unroll
            for (int nt = 0; nt < 2; nt++) {
                int n = n0 + wn * 16 + nt * 8 + (lane & 3) * 2;
                Y[(size_t)m * H3 + n]     = acc[mt][nt][half * 2 + 0];
                Y[(size_t)m * H3 + n + 1] = acc[mt][nt][half * 2 + 1];
            }
        }
}

// ===== linear on HMMA: Y[64,1024] = X@W^T + bias (6-term split), optional epilogues =====
__global__ __launch_bounds__(256) void lin_mma(
    const bf16* __restrict__ x3, int xstride, long long xsplit_stride,
    const bf16* __restrict__ W3, const float* __restrict__ bias, int K,
    float* __restrict__ Y, int reset_keys, int write_split)
{
    __shared__ __align__(16) bf16 Asm[3][64][GP];
    __shared__ __align__(16) bf16 Wsm[3][64][GP];
    const int tid = threadIdx.x, lane = tid & 31, warp = tid >> 5;
    const int wm = warp >> 2, wn = warp & 3;
    const int n0 = blockIdx.x * 64;
    if (reset_keys && blockIdx.x == 0 && tid < B) g_keys[tid] = 0ULL;
    const bf16* Asrc[3] = { x3, x3 + xsplit_stride, x3 + 2 * xsplit_stride };
    const size_t WSp = (size_t)H * K;
    const bf16* Wsrc[3] = { W3, W3 + WSp, W3 + 2 * WSp };
    const int row = tid >> 2, q = tid & 3;
    uint4 pa[3], pw[3];
#pragma unroll
    for (int sp = 0; sp < 3; sp++) {
        pa[sp] = *(const uint4*)(Asrc[sp] + (size_t)row * xstride + q * 8);
        pw[sp] = *(const uint4*)(Wsrc[sp] + (size_t)(n0 + row) * K + q * 8);
    }
    float acc[2][2][4];
#pragma unroll
    for (int mt = 0; mt < 2; mt++)
#pragma unroll
        for (int nt = 0; nt < 2; nt++)
#pragma unroll
            for (int r = 0; r < 4; r++) acc[mt][nt][r] = 0.f;
    const int NC = K / 32;
    for (int c = 0; c < NC; c++) {
        __syncthreads();
#pragma unroll
        for (int sp = 0; sp < 3; sp++) {
            *(uint4*)(&Asm[sp][row][q * 8]) = pa[sp];
            *(uint4*)(&Wsm[sp][row][q * 8]) = pw[sp];
        }
        __syncthreads();
        if (c < NC - 1) {
            int k0 = (c + 1) * 32;
#pragma unroll
            for (int sp = 0; sp < 3; sp++) {
                pa[sp] = *(const uint4*)(Asrc[sp] + (size_t)row * xstride + k0 + q * 8);
                pw[sp] = *(const uint4*)(Wsrc[sp] + (size_t)(n0 + row) * K + k0 + q * 8);
            }
        }
#pragma unroll
        for (int k16 = 0; k16 < 2; k16++) {
            uint32_t af[3][2][4];
#pragma unroll
            for (int sp = 0; sp < 3; sp++)
#pragma unroll
                for (int mt = 0; mt < 2; mt++)
                    ldmA(af[sp][mt], smem_u32(&Asm[sp][wm * 32 + mt * 16 + (lane & 15)][k16 * 16 + (lane >> 4) * 8]));
#pragma unroll
            for (int nt = 0; nt < 2; nt++) {
                uint32_t bfr[3][2];
#pragma unroll
                for (int sp = 0; sp < 3; sp++)
                    ldmB(bfr[sp], smem_u32(&Wsm[sp][wn * 16 + nt * 8 + (lane & 7)][k16 * 16 + ((lane >> 3) & 1) * 8]));
#pragma unroll
                for (int mt = 0; mt < 2; mt++) {
                    mma16816(acc[mt][nt], af[0][mt], bfr[0]);
                    mma16816(acc[mt][nt], af[0][mt], bfr[1]);
                    mma16816(acc[mt][nt], af[1][mt], bfr[0]);
                    mma16816(acc[mt][nt], af[0][mt], bfr[2]);
                    mma16816(acc[mt][nt], af[1][mt], bfr[1]);
                    mma16816(acc[mt][nt], af[2][mt], bfr[0]);
                }
            }
        }
    }
#pragma unroll
    for (int mt = 0; mt < 2; mt++)
#pragma unroll
        for (int half = 0; half < 2; half++) {
            int m = wm * 32 + mt * 16 + half * 8 + (lane >> 2);
#pragma unroll
            for (int nt = 0; nt < 2; nt++) {
                int n = n0 + wn * 16 + nt * 8 + (lane & 3) * 2;
#pragma unroll
                for (int e = 0; e < 2; e++) {
                    float v = acc[mt][nt][half * 2 + e] + bias[n + e];
                    size_t idx = (size_t)m * H + n + e;
                    Y[idx] = v;
                    if (write_split) {
                        bf16 hv, mv, lv; split3(v, hv, mv, lv);
                        g_ch[idx] = hv; g_cm[idx] = mv; g_cl[idx] = lv;
                    }
                }
            }
        }
}

// ===== GRU gate epilogue (fp32 recurrence; emits bf16 splits of h; optional cat splits) =====
__global__ __launch_bounds__(1024) void gru_epi(
    const float* __restrict__ bih, const float* __restrict__ bhh,
    const float* __restrict__ hin, float* __restrict__ hout,
    bf16* __restrict__ sp3, float* __restrict__ cat_aux, int write_cats)
{
    const int b = blockIdx.x, j = threadIdx.x;
    const size_t rb = (size_t)b * H3;
    float gi_r = g_Ygi[rb + j], gi_z = g_Ygi[rb + H + j], gi_n = g_Ygi[rb + 2 * H + j];
    float gh_r = g_Ygh[rb + j], gh_z = g_Ygh[rb + H + j], gh_n = g_Ygh[rb + 2 * H + j];
    float hp = hin[(size_t)b * H + j];
    float r = sigmoidf_((gi_r + bih[j]) + (gh_r + bhh[j]));
    float z = sigmoidf_((gi_z + bih[H + j]) + (gh_z + bhh[H + j]));
    float n = tanhf((gi_n + bih[2 * H + j]) + r * (gh_n + bhh[2 * H + j]));
    float h = (1.f - z) * n + z * hp;
    size_t idx = (size_t)b * H + j;
    hout[idx] = h;
    bf16 hv, mv, lv; split3(h, hv, mv, lv);
    sp3[idx] = hv; sp3[BH + idx] = mv; sp3[2 * BH + idx] = lv;
    if (cat_aux) cat_aux[(size_t)b * 2 * H + H + j] = h;
    if (write_cats) {
        size_t cidx = (size_t)b * 2 * H + H + j;
        g_cats[cidx] = hv; g_cats[(size_t)B * 2 * H + cidx] = mv;
        g_cats[2 * (size_t)B * 2 * H + cidx] = lv;
    }
}

// ===== attention (4-way partial sums in weighted sum; emits cat att splits) =====
__global__ __launch_bounds__(1024) void attn_kernel(
    const float* __restrict__ q, const float* __restrict__ enc,
    float* __restrict__ cat, float* __restrict__ attn_out, int s)
{
    __shared__ float qs[H], wv[TIN], red[256];
    const int b = blockIdx.x, tid = threadIdx.x;
    qs[tid] = q[(size_t)b * H + tid];
    __syncthreads();
    const int warp = tid >> 5, lane = tid & 31;
    for (int t = warp; t < TIN; t += 32) {
        const float* e = enc + (size_t)(t * B + b) * H;
        float sacc = 0.f;
#pragma unroll 4
        for (int k = lane; k < H; k += 32) sacc = fmaf(qs[k], e[k], sacc);
        for (int o = 16; o; o >>= 1) sacc += __shfl_xor_sync(0xffffffffu, sacc, o);
        if (!lane) wv[t] = sacc;
    }
    __syncthreads();
    float v = 0.f, ev = 0.f;
    if (tid < 256) { v = wv[tid]; red[tid] = v; }
    __syncthreads();
    for (int st = 128; st; st >>= 1) { if (tid < st) red[tid] = fmaxf(red[tid], red[tid + st]); __syncthreads(); }
    float mx = red[0]; __syncthreads();
    if (tid < 256) { ev = expf(v - mx); red[tid] = ev; }
    __syncthreads();
    for (int st = 128; st; st >>= 1) { if (tid < st) red[tid] += red[tid + st]; __syncthreads(); }
    if (tid < 256) {
        float aw = ev / red[0];
        wv[tid] = aw;
        attn_out[((size_t)b * TIN + tid) * TGT + s] = aw;
    }
    __syncthreads();
    {
        int k = tid;
        float a0 = 0.f, a1 = 0.f, a2 = 0.f, a3 = 0.f;
        for (int t = 0; t < TIN; t += 4) {
            a0 = fmaf(wv[t],     enc[(size_t)((t)     * B + b) * H + k], a0);
            a1 = fmaf(wv[t + 1], enc[(size_t)((t + 1) * B + b) * H + k], a1);
            a2 = fmaf(wv[t + 2], enc[(size_t)((t + 2) * B + b) * H + k], a2);
            a3 = fmaf(wv[t + 3], enc[(size_t)((t + 3) * B + b) * H + k], a3);
        }
        float sacc = (a0 + a1) + (a2 + a3);
        size_t cidx = (size_t)b * 2 * H + k;
        cat[cidx] = sacc;
        bf16 hv, mv, lv; split3(sacc, hv, mv, lv);
        g_cats[cidx] = hv; g_cats[(size_t)B * 2 * H + cidx] = mv;
        g_cats[2 * (size_t)B * 2 * H + cidx] = lv;
    }
}

// ===== fc on HMMA (proven R12, unchanged) =====
#define AP 40
__global__ __launch_bounds__(256) void fc_mma(
    const bf16* __restrict__ Wh, const bf16* __restrict__ Wm,
    const bf16* __restrict__ Wl, const float* __restrict__ bfc,
    float* __restrict__ out, int s)
{
    __shared__ __align__(16) bf16 Asm[3][64][AP];
    __shared__ __align__(16) bf16 Wsm[3][128][AP];
    __shared__ ULL skeys[B];
    const int tid = threadIdx.x, lane = tid & 31, warp = tid >> 5;
    const int wm = warp >> 2, wn = warp & 3;
    const int n0 = blockIdx.x * 128;
    if (tid < B) skeys[tid] = 0ULL;
    const bf16* Asrc[3] = { g_ch, g_cm, g_cl };
    const bf16* Wsrc[3] = { Wh, Wm, Wl };
    const int arow = tid >> 2, aq = tid & 3;
    uint4 pa[3], pw[3][2];
#pragma unroll
    for (int sp = 0; sp < 3; sp++) {
        pa[sp] = *(const uint4*)(Asrc[sp] + (size_t)arow * H + aq * 8);
#pragma unroll
        for (int t = 0; t < 2; t++) {
            int i = tid + t * 256, row = i >> 2, q = i & 3;
            pw[sp][t] = *(const uint4*)(Wsrc[sp] + (size_t)(n0 + row) * H + q * 8);
        }
    }
    float acc[2][4][4];
#pragma unroll
    for (int mt = 0; mt < 2; mt++)
#pragma unroll
        for (int nt = 0; nt < 4; nt++)
#pragma unroll
            for (int r = 0; r < 4; r++) acc[mt][nt][r] = 0.f;
    for (int c = 0; c < 32; c++) {
        __syncthreads();
#pragma unroll
        for (int sp = 0; sp < 3; sp++) {
            *(uint4*)(&Asm[sp][arow][aq * 8]) = pa[sp];
#pragma unroll
            for (int t = 0; t < 2; t++) {
                int i = tid + t * 256, row = i >> 2, q = i & 3;
                *(uint4*)(&Wsm[sp][row][q * 8]) = pw[sp][t];
            }
        }
        __syncthreads();
        if (c < 31) {
            int k0 = (c + 1) * 32;
#pragma unroll
            for (int sp = 0; sp < 3; sp++) {
                pa[sp] = *(const uint4*)(Asrc[sp] + (size_t)arow * H + k0 + aq * 8);
#pragma unroll
                for (int t = 0; t < 2; t++) {
                    int i = tid + t * 256, row = i >> 2, q = i & 3;
                    pw[sp][t] = *(const uint4*)(Wsrc[sp] + (size_t)(n0 + row) * H + k0 + q * 8);
                }
            }
        }
#pragma unroll
        for (int k16 = 0; k16 < 2; k16++) {
            uint32_t af[3][2][4];
#pragma unroll
            for (int sp = 0; sp < 3; sp++)
#pragma unroll
                for (int mt = 0; mt < 2; mt++)
                    ldmA(af[sp][mt], smem_u32(&Asm[sp][wm * 32 + mt * 16 + (lane & 15)][k16 * 16 + (lane >> 4) * 8]));
#pragma unroll
            for (int nt = 0; nt < 4; nt++) {
                uint32_t bfr[3][2];
#pragma unroll
                for (int sp = 0; sp < 3; sp++)
                    ldmB(bfr[sp], smem_u32(&Wsm[sp][wn * 32 + nt * 8 + (lane & 7)][k16 * 16 + ((lane >> 3) & 1) * 8]));
#pragma unroll
                for (int mt = 0; mt < 2; mt++) {
                    mma16816(acc[mt][nt], af[0][mt], bfr[0]);
                    mma16816(acc[mt][nt], af[0][mt], bfr[1]);
                    mma16816(acc[mt][nt], af[1][mt], bfr[0]);
                    mma16816(acc[mt][nt], af[0][mt], bfr[2]);
                    mma16816(acc[mt][nt], af[1][mt], bfr[1]);
                    mma16816(acc[mt][nt], af[2][mt], bfr[0]);
                }
            }
        }
    }
#pragma unroll
    for (int mt = 0; mt < 2; mt++)
#pragma unroll
        for (int half = 0; half < 2; half++) {
            int m = wm * 32 + mt * 16 + half * 8 + (lane >> 2);
            float* orow = out + ((size_t)m * TGT + s) * V;
            ULL rmax = 0ULL;
#pragma unroll
            for (int nt = 0; nt < 4; nt++) {
                int n = n0 + wn * 32 + nt * 8 + (lane & 3) * 2;
                float v0 = acc[mt][nt][half * 2 + 0] + bfc[n];
                float v1 = acc[mt][nt][half * 2 + 1] + bfc[n + 1];
                *(float2*)(orow + n) = make_float2(v0, v1);
                ULL k0b = ((ULL)ord32(v0) << 15) | (ULL)(V - 1 - n);
                ULL k1b = ((ULL)ord32(v1) << 15) | (ULL)(V - 2 - n);
                if (k0b > rmax) rmax = k0b;
                if (k1b > rmax) rmax = k1b;
            }
            atomicMax(&skeys[m], rmax);
        }
    __syncthreads();
    if (tid < B) atomicMax(&g_keys[tid], skeys[tid]);
}

// ===== host =====
extern "C" void kernel_launch(void* const* d_in, const int* in_sizes, int n_in,
                              void* d_out_, int out_size) {
    const float* x = (const float*)d_in[0];
    const float* embed = (const float*)d_in[1];
    const float* eWih0 = (const float*)d_in[2];  const float* eWhh0 = (const float*)d_in[3];
    const float* ebih0 = (const float*)d_in[4];  const float* ebhh0 = (const float*)d_in[5];
    const float* eWih1 = (const float*)d_in[6];  const float* eWhh1 = (const float*)d_in[7];
    const float* ebih1 = (const float*)d_in[8];  const float* ebhh1 = (const float*)d_in[9];
    const float* dWih0 = (const float*)d_in[10]; const float* dWhh0 = (const float*)d_in[11];
    const float* dbih0 = (const float*)d_in[12]; const float* dbhh0 = (const float*)d_in[13];
    const float* dWih1 = (const float*)d_in[14]; const float* dWhh1 = (const float*)d_in[15];
    const float* dbih1 = (const float*)d_in[16]; const float* dbhh1 = (const float*)d_in[17];
    const float* Wq = (const float*)d_in[18];    const float* bq = (const float*)d_in[19];
    const float* Wc = (const float*)d_in[20];    const float* bc = (const float*)d_in[21];
    const float* Wfc = (const float*)d_in[22];   const float* bfc = (const float*)d_in[23];
    float* out = (float*)d_out_;
    const size_t HID_OFF = (size_t)B * TGT * V;
    const size_t ATTN_OFF = HID_OFF + (size_t)2 * BH;

    float *gi0, *gi1, *h0seq, *enc, *dh0, *dh1, *q, *cat;
    bf16 *xe, *h0s, *h1s, *cats;
    cudaGetSymbolAddress((void**)&gi0, g_gi0);
    cudaGetSymbolAddress((void**)&gi1, g_gi1);
    cudaGetSymbolAddress((void**)&h0seq, g_h0seq);
    cudaGetSymbolAddress((void**)&enc, g_enc);
    cudaGetSymbolAddress((void**)&dh0, g_dh0);
    cudaGetSymbolAddress((void**)&dh1, g_dh1);
    cudaGetSymbolAddress((void**)&q, g_q);
    cudaGetSymbolAddress((void**)&cat, g_cat);
    cudaGetSymbolAddress((void**)&xe, g_xe);
    cudaGetSymbolAddress((void**)&h0s, g_h0s);
    cudaGetSymbolAddress((void**)&h1s, g_h1s);
    cudaGetSymbolAddress((void**)&cats, g_cats);
    bf16* Wfh = (bf16*)gi0;
    bf16* Wfm = Wfh + (size_t)V * H;
    bf16* Wfl = Wfm + (size_t)V * H;
    const size_t WS = (size_t)H3 * H;
    bf16* wsp = (bf16*)gi1;
    bf16* Wih0s = wsp;
    bf16* Whh0s = wsp + 3 * WS;
    bf16* Wih1s = wsp + 6 * WS;
    bf16* Whh1s = wsp + 9 * WS;
    bf16* Wqs   = wsp + 12 * WS;                       // 3 x H*H
    bf16* Wcs   = Wqs + 3 * (size_t)H * H;             // 3 x H*2H

    const int ENC_SMEM = (24 * WS_PITCH + 64 * XS_PITCH) * (int)sizeof(float);
    cudaFuncSetAttribute(enc_recur_kernel, cudaFuncAttributeMaxDynamicSharedMemorySize, ENC_SMEM);

    // ---- encoder ----
    gemm2_tn<<<dim3(H3/128, (B*TIN)/64), 256>>>(x, eWih0, ebih0, gi0, F, F, F, H3);
    enc_recur_kernel<<<128, 256, ENC_SMEM>>>(gi0, (long long)H3, (long long)TIN * H3, eWhh0, ebhh0, h0seq);
    gemm2_tn<<<dim3(H3/128, (B*TIN)/64), 256>>>(h0seq, eWih1, ebih1, gi1, H, H, H, H3);
    enc_recur_kernel<<<128, 256, ENC_SMEM>>>(gi1, (long long)B * H3, (long long)H3, eWhh1, ebhh1, enc);

    // ---- one-time splits (gi0/gi1 free after encoder) ----
    split_w_kernel<<<1024, 256>>>(Wfc, Wfh, Wfm, Wfl, (size_t)V * H);
    split_w_kernel<<<512, 256>>>(dWih0, Wih0s, Wih0s + WS, Wih0s + 2 * WS, WS);
    split_w_kernel<<<512, 256>>>(dWhh0, Whh0s, Whh0s + WS, Whh0s + 2 * WS, WS);
    split_w_kernel<<<512, 256>>>(dWih1, Wih1s, Wih1s + WS, Wih1s + 2 * WS, WS);
    split_w_kernel<<<512, 256>>>(dWhh1, Whh1s, Whh1s + WS, Whh1s + 2 * WS, WS);
    split_w_kernel<<<256, 256>>>(Wq, Wqs, Wqs + (size_t)H * H, Wqs + 2 * (size_t)H * H, (size_t)H * H);
    split_w_kernel<<<512, 256>>>(Wc, Wcs, Wcs + (size_t)H * 2 * H, Wcs + 2 * (size_t)H * 2 * H, (size_t)H * 2 * H);
    split_w_kernel<<<256, 256>>>(h0seq + (size_t)(TIN - 1) * BH,
        h0s + 3 * BH, h0s + 4 * BH, h0s + 5 * BH, (size_t)BH);
    split_w_kernel<<<256, 256>>>(enc + (size_t)(TIN - 1) * BH,
        h1s + 3 * BH, h1s + 4 * BH, h1s + 5 * BH, (size_t)BH);

    // ---- decoder ----
    for (int s = 0; s < TGT; s++) {
        const int p0 = s & 1, p1 = (s + 1) & 1;
        const float* h0in = s ? (dh0 + (size_t)p1 * BH) : (h0seq + (size_t)(TIN - 1) * BH);
        const float* h1in = s ? (dh1 + (size_t)p1 * BH) : (enc + (size_t)(TIN - 1) * BH);
        float* h0out = dh0 + (size_t)p0 * BH;
        float* h1out = dh1 + (size_t)p0 * BH;

        embsplit<<<B, 256>>>(embed, s);
        mma_gemm<<<dim3(H3/64, 2), 256>>>(xe, h0s + (size_t)p1 * 3 * BH, Wih0s, Whh0s);
        gru_epi<<<B, 1024>>>(dbih0, dbhh0, h0in, h0out, h0s + (size_t)p0 * 3 * BH, nullptr, 0);
        mma_gemm<<<dim3(H3/64, 2), 256>>>(h0s + (size_t)p0 * 3 * BH, h1s + (size_t)p1 * 3 * BH, Wih1s, Whh1s);
        gru_epi<<<B, 1024>>>(dbih1, dbhh1, h1in, h1out, h1s + (size_t)p0 * 3 * BH, cat, 1);
        lin_mma<<<H/64, 256>>>(h1s + (size_t)p0 * 3 * BH, H, (long long)BH, Wqs, bq, H, q, 0, 0);
        attn_kernel<<<B, 1024>>>(q, enc, cat, out + ATTN_OFF, s);
        lin_mma<<<H/64, 256>>>(cats, 2 * H, (long long)B * 2 * H, Wcs, bc, 2 * H, g_comb, 1, 1);
        fc_mma<<<V / 128, 256>>>(Wfh, Wfm, Wfl, bfc, out, s);
    }
    cudaMemcpyAsync(out + HID_OFF,      dh0 + BH, (size_t)BH * sizeof(float), cudaMemcpyDeviceToDevice);
    cudaMemcpyAsync(out + HID_OFF + BH, dh1 + BH, (size_t)BH * sizeof(float), cudaMemcpyDeviceToDevice);
}